// round 2
// baseline (speedup 1.0000x reference)
#include <cuda_runtime.h>
#include <cstdint>

// ---------------------------------------------------------------------------
// IonisGateV26: fused gated MLP
//   t = mish(mish(x[:, :15] @ tw1 + tb1) @ tw2 + tb2)          (B,256)
//   base = head_{band}(t)   (only the selected band's head is computed)
//   out = base + gate_sun * mono(x_sfi) + gate_storm * mono(x_kp)
// Two kernels: trunk (GEMM1+GEMM2 -> t scratch), heads (band-grouped head GEMM
// + gates + monotonic MLPs). fp32 with packed fma.rn.f32x2 throughout.
// ---------------------------------------------------------------------------

#define B_MAX 262144
__device__ float g_tbuf[(size_t)B_MAX * 256];   // t scratch, 256MB

// ---------------- math helpers ----------------
__device__ __forceinline__ float mishf(float v){
    // mish(v) = v * tanh(softplus(v)) = v * e(e+2) / (e(e+2)+2), e = exp(v)
    if (v > 20.f) return v;
    float e = __expf(v);
    float n = e * (e + 2.f);
    return v * n / (n + 2.f);
}
__device__ __forceinline__ float softplusf(float v){
    if (v > 20.f) return v;
    return log1pf(__expf(v));
}
__device__ __forceinline__ float sigmoidf_(float v){
    return 1.f / (1.f + __expf(-v));
}

// ---------------- packed f32x2 helpers ----------------
__device__ __forceinline__ unsigned long long pack2(float a, float b){
    unsigned long long r;
    asm("mov.b64 %0, {%1, %2};" : "=l"(r)
        : "r"(__float_as_uint(a)), "r"(__float_as_uint(b)));
    return r;
}
__device__ __forceinline__ void fma2(unsigned long long &d,
                                     unsigned long long a, unsigned long long b){
    asm("fma.rn.f32x2 %0, %1, %2, %0;" : "+l"(d) : "l"(a), "l"(b));
}
__device__ __forceinline__ float lo2(unsigned long long v){
    return __uint_as_float((unsigned)(v & 0xffffffffull));
}
__device__ __forceinline__ float hi2(unsigned long long v){
    return __uint_as_float((unsigned)(v >> 32));
}

// ---------------------------------------------------------------------------
// Kernel 1: trunk. 64 rows/block, 256 threads.
// smem: h1 (64x512 f32, 128KB) | wbuf (16384 f32: tw1 then tw2 chunks, 64KB)
//       | xs (64x16, 4KB)  => 196KB dynamic smem, 1 block/SM.
// GEMM2: C(64x256) = h1(64x512) @ tw2(512x256), thread tile 8 rows x 8 cols,
// col-pair f32x2 accumulators. Warp = one 8-row group -> A loads are smem
// broadcasts (conflict-free).
// ---------------------------------------------------------------------------
__global__ __launch_bounds__(256, 1)
void trunk_kernel(const float* __restrict__ x,
                  const float* __restrict__ tw1, const float* __restrict__ tb1,
                  const float* __restrict__ tw2, const float* __restrict__ tb2,
                  int B)
{
    extern __shared__ float sm[];
    float* h1s  = sm;             // 64*512
    float* wbuf = sm + 64*512;    // 16384 floats
    float* xs   = wbuf + 16384;   // 64*16
    const int tid = threadIdx.x;
    const int r0  = blockIdx.x * 64;

    // stage x_deep (64 x 15) and tw1 (15 x 512)
    for (int i = tid; i < 64*15; i += 256){
        int r = i / 15, c = i - r*15;
        xs[r*16 + c] = x[(size_t)(r0 + r)*18 + c];
    }
    for (int i = tid; i < 15*512; i += 256) wbuf[i] = __ldg(&tw1[i]);
    __syncthreads();

    // GEMM1 (K=15) + mish -> h1s
    for (int idx = tid; idx < 64*512; idx += 256){
        int r = idx >> 9, c = idx & 511;
        float acc = __ldg(&tb1[c]);
        #pragma unroll
        for (int d = 0; d < 15; d++)
            acc = fmaf(xs[r*16 + d], wbuf[d*512 + c], acc);
        h1s[idx] = mishf(acc);
    }

    // GEMM2: thread (tx, ty): rows ty*8..+7, cols tx*8..+7
    const int tx = tid & 31, ty = tid >> 5;
    unsigned long long acc[8][4];
    #pragma unroll
    for (int r = 0; r < 8; r++)
        #pragma unroll
        for (int p = 0; p < 4; p++) acc[r][p] = 0ull;

    float4* wbuf4 = (float4*)wbuf;
    for (int kc = 0; kc < 512; kc += 64){
        __syncthreads();   // previous chunk (or phase-1 tw1 / h1s writes) settled
        const float4* src = (const float4*)(tw2 + (size_t)kc*256);
        for (int i = tid; i < (64*256)/4; i += 256) wbuf4[i] = __ldg(&src[i]);
        __syncthreads();
        #pragma unroll 4
        for (int kk = 0; kk < 64; kk++){
            float4 b0 = wbuf4[kk*64 + tx*2];
            float4 b1 = wbuf4[kk*64 + tx*2 + 1];
            unsigned long long p0 = pack2(b0.x, b0.y), p1 = pack2(b0.z, b0.w);
            unsigned long long p2 = pack2(b1.x, b1.y), p3 = pack2(b1.z, b1.w);
            #pragma unroll
            for (int r = 0; r < 8; r++){
                float a = h1s[(ty*8 + r)*512 + kc + kk];   // warp-broadcast
                unsigned long long as = pack2(a, a);
                fma2(acc[r][0], as, p0); fma2(acc[r][1], as, p1);
                fma2(acc[r][2], as, p2); fma2(acc[r][3], as, p3);
            }
        }
    }

    // epilogue: + tb2, mish, write t
    #pragma unroll
    for (int r = 0; r < 8; r++){
        size_t row = (size_t)(r0 + ty*8 + r);
        #pragma unroll
        for (int p = 0; p < 4; p++){
            int c = tx*8 + p*2;
            float v0 = lo2(acc[r][p]) + __ldg(&tb2[c]);
            float v1 = hi2(acc[r][p]) + __ldg(&tb2[c+1]);
            g_tbuf[row*256 + c]     = mishf(v0);
            g_tbuf[row*256 + c + 1] = mishf(v1);
        }
    }
}

// ---------------------------------------------------------------------------
// Kernel 2: heads + gates + monotonic MLPs. 256 rows/block, 256 threads.
// Rows bucketed by band in smem; each warp processes groups of 8 same-band
// rows so hw1[band] (128KB) is reused 8x per pass and stays L1/L2-resident.
// Gate branch short-circuits at runtime when sw2/stw2 == 0 (checked on
// device, so the kernel is correct for arbitrary weights).
// ---------------------------------------------------------------------------
__global__ __launch_bounds__(256)
void heads_kernel(const float* __restrict__ x,
                  const float* __restrict__ hw1, const float* __restrict__ hb1,
                  const float* __restrict__ hw2, const float* __restrict__ hb2,
                  const float* __restrict__ sw1, const float* __restrict__ sb1,
                  const float* __restrict__ sw2, const float* __restrict__ sb2,
                  const float* __restrict__ stw1, const float* __restrict__ stb1,
                  const float* __restrict__ stw2, const float* __restrict__ stb2,
                  const float* __restrict__ sun_w1, const float* __restrict__ sun_b1,
                  const float* __restrict__ sun_w2, const float* __restrict__ sun_b2,
                  const float* __restrict__ storm_w1, const float* __restrict__ storm_b1,
                  const float* __restrict__ storm_w2, const float* __restrict__ storm_b2,
                  float* __restrict__ out, int B)
{
    __shared__ unsigned short lists[9*256];
    __shared__ int   counts[9];
    __shared__ float hb1s[128], hw2s[128];
    __shared__ float partial[256];
    __shared__ float sunw1s[8], sunb1s[8], sunw2s[8];
    __shared__ float stmw1s[8], stmb1s[8], stmw2s[8];
    __shared__ float consts[4];   // sun_b2, storm_b2, sunGate, stormGate
    __shared__ int   zflags[2];

    const int tid = threadIdx.x;
    const int r0  = blockIdx.x * 256;
    const int row = r0 + tid;

    if (tid < 8){
        sunw1s[tid] = softplusf(sun_w1[tid]);
        sunb1s[tid] = sun_b1[tid];
        sunw2s[tid] = softplusf(sun_w2[tid]);
        stmw1s[tid] = softplusf(storm_w1[tid]);
        stmb1s[tid] = storm_b1[tid];
        stmw2s[tid] = softplusf(storm_w2[tid]);
    }
    if (tid == 0){
        consts[0] = sun_b2[0];
        consts[1] = storm_b2[0];
        int z1 = 1, z2 = 1;
        for (int j = 0; j < 64; j++){
            if (sw2[j]  != 0.f) z1 = 0;
            if (stw2[j] != 0.f) z2 = 0;
        }
        zflags[0] = z1; zflags[1] = z2;
        consts[2] = sigmoidf_(sb2[0]);
        consts[3] = sigmoidf_(stb2[0]);
    }
    if (tid < 9) counts[tid] = 0;
    __syncthreads();

    // per-row scalar path
    float sfi = x[(size_t)row*18 + 15];
    float kp  = x[(size_t)row*18 + 16];
    int band  = (int)x[(size_t)row*18 + 17];
    band = min(max(band, 0), 8);

    float sunv = consts[0], stmv = consts[1];
    #pragma unroll
    for (int j = 0; j < 8; j++){
        sunv = fmaf(tanhf(fmaf(sfi, sunw1s[j], sunb1s[j])), sunw2s[j], sunv);
        stmv = fmaf(tanhf(fmaf(kp,  stmw1s[j], stmb1s[j])), stmw2s[j], stmv);
    }

    float sg, stg;
    if (zflags[0]) sg = consts[2];
    else {  // general (cold) path: correct for arbitrary sw2
        float logit = sb2[0];
        const float* tr = g_tbuf + (size_t)row*256;
        for (int j = 0; j < 64; j++){
            float s = sb1[j];
            for (int d = 0; d < 256; d++) s = fmaf(tr[d], sw1[d*64 + j], s);
            logit = fmaf(mishf(s), sw2[j], logit);
        }
        sg = sigmoidf_(logit);
    }
    if (zflags[1]) stg = consts[3];
    else {
        float logit = stb2[0];
        const float* tr = g_tbuf + (size_t)row*256;
        for (int j = 0; j < 64; j++){
            float s = stb1[j];
            for (int d = 0; d < 256; d++) s = fmaf(tr[d], stw1[d*64 + j], s);
            logit = fmaf(mishf(s), stw2[j], logit);
        }
        stg = sigmoidf_(logit);
    }
    partial[tid] = sg*sunv + stg*stmv;

    int pos = atomicAdd(&counts[band], 1);
    lists[band*256 + pos] = (unsigned short)tid;

    const int lane = tid & 31, wid = tid >> 5;

    for (int k = 0; k < 9; k++){
        __syncthreads();            // prior band's groups done, counts visible
        int cnt = counts[k];
        if (cnt > 0 && tid < 128){
            hb1s[tid] = hb1[k*128 + tid];
            hw2s[tid] = hw2[k*128 + tid];
        }
        __syncthreads();
        if (cnt == 0) continue;
        float hb2k = __ldg(&hb2[k]);
        const float* W = hw1 + (size_t)k*32768;   // (256,128) row-major over d

        for (int g = wid; g*8 < cnt; g += 8){
            int m = min(8, cnt - g*8);
            int lr[8];
            #pragma unroll
            for (int j = 0; j < 8; j++)
                lr[j] = lists[k*256 + g*8 + (j < m ? j : m-1)];

            unsigned long long acc[8][2];
            #pragma unroll
            for (int j = 0; j < 8; j++){ acc[j][0] = 0ull; acc[j][1] = 0ull; }

            for (int d = 0; d < 256; d += 4){
                float4 w0 = __ldg((const float4*)(W + (size_t)(d+0)*128 + lane*4));
                float4 w1 = __ldg((const float4*)(W + (size_t)(d+1)*128 + lane*4));
                float4 w2 = __ldg((const float4*)(W + (size_t)(d+2)*128 + lane*4));
                float4 w3 = __ldg((const float4*)(W + (size_t)(d+3)*128 + lane*4));
                unsigned long long b00 = pack2(w0.x,w0.y), b01 = pack2(w0.z,w0.w);
                unsigned long long b10 = pack2(w1.x,w1.y), b11 = pack2(w1.z,w1.w);
                unsigned long long b20 = pack2(w2.x,w2.y), b21 = pack2(w2.z,w2.w);
                unsigned long long b30 = pack2(w3.x,w3.y), b31 = pack2(w3.z,w3.w);
                #pragma unroll
                for (int j = 0; j < 8; j++){
                    float4 tv = __ldg((const float4*)(g_tbuf + (size_t)(r0 + lr[j])*256 + d));
                    unsigned long long a0 = pack2(tv.x,tv.x), a1 = pack2(tv.y,tv.y);
                    unsigned long long a2 = pack2(tv.z,tv.z), a3 = pack2(tv.w,tv.w);
                    fma2(acc[j][0], a0, b00); fma2(acc[j][1], a0, b01);
                    fma2(acc[j][0], a1, b10); fma2(acc[j][1], a1, b11);
                    fma2(acc[j][0], a2, b20); fma2(acc[j][1], a2, b21);
                    fma2(acc[j][0], a3, b30); fma2(acc[j][1], a3, b31);
                }
            }

            int c0 = lane*4;
            #pragma unroll
            for (int j = 0; j < 8; j++){
                float s = mishf(lo2(acc[j][0]) + hb1s[c0    ]) * hw2s[c0    ]
                        + mishf(hi2(acc[j][0]) + hb1s[c0 + 1]) * hw2s[c0 + 1]
                        + mishf(lo2(acc[j][1]) + hb1s[c0 + 2]) * hw2s[c0 + 2]
                        + mishf(hi2(acc[j][1]) + hb1s[c0 + 3]) * hw2s[c0 + 3];
                #pragma unroll
                for (int o = 16; o > 0; o >>= 1)
                    s += __shfl_down_sync(0xffffffffu, s, o);
                if (lane == 0 && j < m)
                    out[r0 + lr[j]] = s + hb2k + partial[lr[j]];
            }
        }
    }
}

// ---------------------------------------------------------------------------
extern "C" void kernel_launch(void* const* d_in, const int* in_sizes, int n_in,
                              void* d_out, int out_size)
{
    const float* x       = (const float*)d_in[0];
    const float* tw1     = (const float*)d_in[1];
    const float* tb1     = (const float*)d_in[2];
    const float* tw2     = (const float*)d_in[3];
    const float* tb2     = (const float*)d_in[4];
    const float* hw1     = (const float*)d_in[5];
    const float* hb1     = (const float*)d_in[6];
    const float* hw2     = (const float*)d_in[7];
    const float* hb2     = (const float*)d_in[8];
    const float* sw1     = (const float*)d_in[9];
    const float* sb1     = (const float*)d_in[10];
    const float* sw2     = (const float*)d_in[11];
    const float* sb2     = (const float*)d_in[12];
    const float* stw1    = (const float*)d_in[13];
    const float* stb1    = (const float*)d_in[14];
    const float* stw2    = (const float*)d_in[15];
    const float* stb2    = (const float*)d_in[16];
    const float* sun_w1  = (const float*)d_in[17];
    const float* sun_b1  = (const float*)d_in[18];
    const float* sun_w2  = (const float*)d_in[19];
    const float* sun_b2  = (const float*)d_in[20];
    const float* storm_w1= (const float*)d_in[21];
    const float* storm_b1= (const float*)d_in[22];
    const float* storm_w2= (const float*)d_in[23];
    const float* storm_b2= (const float*)d_in[24];
    float* out = (float*)d_out;

    int B = in_sizes[0] / 18;

    size_t smem1 = (size_t)(64*512 + 16384 + 64*16) * sizeof(float);  // 196KB
    cudaFuncSetAttribute(trunk_kernel,
                         cudaFuncAttributeMaxDynamicSharedMemorySize, (int)smem1);

    trunk_kernel<<<B/64, 256, smem1>>>(x, tw1, tb1, tw2, tb2, B);
    heads_kernel<<<B/256, 256>>>(x, hw1, hb1, hw2, hb2,
                                 sw1, sb1, sw2, sb2,
                                 stw1, stb1, stw2, stb2,
                                 sun_w1, sun_b1, sun_w2, sun_b2,
                                 storm_w1, storm_b1, storm_w2, storm_b2,
                                 out, B);
}

// round 3
// speedup vs baseline: 1.5391x; 1.5391x over previous
#include <cuda_runtime.h>
#include <cstdint>

// ---------------------------------------------------------------------------
// IonisGateV26: fused gated MLP.
//  K1 trunk: t = mish(mish(x@tw1+tb1)@tw2+tb2) -> g_tbuf. cp.async
//            double-buffered tw2 chunks, f32x2 FMA register tile.
//  K2 heads: band-bucketed rows, flattened (band,group) work-list across all
//            warps; selected head GEMM + gates + monotonic MLPs.
// ---------------------------------------------------------------------------

#define B_MAX 262144
__device__ float g_tbuf[(size_t)B_MAX * 256];   // t scratch, 256MB

// ---------------- math helpers ----------------
__device__ __forceinline__ float mishf(float v){
    if (v > 20.f) return v;
    float e = __expf(v);
    float n = e * (e + 2.f);
    return v * n / (n + 2.f);
}
__device__ __forceinline__ float softplusf(float v){
    if (v > 20.f) return v;
    return log1pf(__expf(v));
}
__device__ __forceinline__ float sigmoidf_(float v){
    return 1.f / (1.f + __expf(-v));
}

// ---------------- packed f32x2 helpers ----------------
__device__ __forceinline__ unsigned long long pack2(float a, float b){
    unsigned long long r;
    asm("mov.b64 %0, {%1, %2};" : "=l"(r)
        : "r"(__float_as_uint(a)), "r"(__float_as_uint(b)));
    return r;
}
__device__ __forceinline__ void fma2(unsigned long long &d,
                                     unsigned long long a, unsigned long long b){
    asm("fma.rn.f32x2 %0, %1, %2, %0;" : "+l"(d) : "l"(a), "l"(b));
}
__device__ __forceinline__ float lo2(unsigned long long v){
    return __uint_as_float((unsigned)(v & 0xffffffffull));
}
__device__ __forceinline__ float hi2(unsigned long long v){
    return __uint_as_float((unsigned)(v >> 32));
}

// ---------------- cp.async helpers ----------------
__device__ __forceinline__ unsigned smem_u32(const void* p){
    unsigned a;
    asm("{ .reg .u64 t; cvta.to.shared.u64 t, %1; cvt.u32.u64 %0, t; }"
        : "=r"(a) : "l"(p));
    return a;
}
__device__ __forceinline__ void cp16(unsigned s, const void* g){
    asm volatile("cp.async.cg.shared.global [%0], [%1], 16;\n" :: "r"(s), "l"(g));
}
__device__ __forceinline__ void cp_commit(){
    asm volatile("cp.async.commit_group;\n" ::: "memory");
}
template<int N> __device__ __forceinline__ void cp_wait(){
    asm volatile("cp.async.wait_group %0;\n" :: "n"(N) : "memory");
}

// ---------------------------------------------------------------------------
// Kernel 1: trunk. 64 rows/block, 256 threads, 1 block/SM.
// smem: h1 (64x512, 128KB) | buf0,buf1 (2 x 8192 f32 = 2 x 32KB tw2 chunks)
//       | xs (64x16, 4KB)  => 196KB.
// GEMM2: C(64x256) = h1(64x512) @ tw2(512x256); thread tile 8x8, f32x2 accs.
// tw2 streamed in 16 chunks of K=32, cp.async double-buffered.
// ---------------------------------------------------------------------------
__global__ __launch_bounds__(256, 1)
void trunk_kernel(const float* __restrict__ x,
                  const float* __restrict__ tw1, const float* __restrict__ tb1,
                  const float* __restrict__ tw2, const float* __restrict__ tb2,
                  int B)
{
    extern __shared__ float sm[];
    float* h1s  = sm;               // 64*512
    float* buf0 = sm + 64*512;      // 8192
    float* buf1 = buf0 + 8192;      // 8192
    float* xs   = buf1 + 8192;      // 64*16
    const int tid = threadIdx.x;
    const int r0  = blockIdx.x * 64;

    // stage x_deep (64 x 15) and tw1 (15 x 512 = 7680 floats, into buf0)
    for (int i = tid; i < 64*15; i += 256){
        int r = i / 15, c = i - r*15;
        xs[r*16 + c] = x[(size_t)(r0 + r)*18 + c];
    }
    for (int i = tid; i < 15*512; i += 256) buf0[i] = __ldg(&tw1[i]);
    __syncthreads();

    // GEMM1 (K=15) + mish -> h1s
    for (int idx = tid; idx < 64*512; idx += 256){
        int r = idx >> 9, c = idx & 511;
        float acc = __ldg(&tb1[c]);
        #pragma unroll
        for (int d = 0; d < 15; d++)
            acc = fmaf(xs[r*16 + d], buf0[d*512 + c], acc);
        h1s[idx] = mishf(acc);
    }
    __syncthreads();   // buf0 reads done; safe to overwrite with tw2 chunk 0

    // GEMM2: thread (tx, ty): rows ty*8..+7, cols tx*8..+7
    const int tx = tid & 31, ty = tid >> 5;
    unsigned long long acc[8][4];
    #pragma unroll
    for (int r = 0; r < 8; r++)
        #pragma unroll
        for (int p = 0; p < 4; p++) acc[r][p] = 0ull;

    // chunk copy: 32 rows x 256 cols = 8192 floats = 2048 x 16B, 8 per thread
    const unsigned b0a = smem_u32(buf0), b1a = smem_u32(buf1);
    auto issue_chunk = [&](int c){
        unsigned dst = (c & 1) ? b1a : b0a;
        const float* src = tw2 + (size_t)c * 32 * 256;
        #pragma unroll
        for (int i = 0; i < 8; i++){
            int e = tid + i * 256;             // float4 index
            cp16(dst + e * 16, src + e * 4);
        }
        cp_commit();
    };

    issue_chunk(0);
    #pragma unroll 1
    for (int c = 0; c < 16; c++){
        if (c + 1 < 16) issue_chunk(c + 1);
        if (c + 1 < 16) cp_wait<1>(); else cp_wait<0>();
        __syncthreads();                        // current chunk visible to all
        const float4* wb4 = (const float4*)((c & 1) ? buf1 : buf0);
        const int kc = c * 32;
        #pragma unroll 4
        for (int kk = 0; kk < 32; kk++){
            float4 b0 = wb4[kk*64 + tx*2];
            float4 b1 = wb4[kk*64 + tx*2 + 1];
            unsigned long long p0 = pack2(b0.x, b0.y), p1 = pack2(b0.z, b0.w);
            unsigned long long p2 = pack2(b1.x, b1.y), p3 = pack2(b1.z, b1.w);
            #pragma unroll
            for (int r = 0; r < 8; r++){
                float a = h1s[(ty*8 + r)*512 + kc + kk];   // warp-broadcast
                unsigned long long as = pack2(a, a);
                fma2(acc[r][0], as, p0); fma2(acc[r][1], as, p1);
                fma2(acc[r][2], as, p2); fma2(acc[r][3], as, p3);
            }
        }
        __syncthreads();   // reads of this buffer done before it is refilled
    }

    // epilogue: + tb2, mish, vectorized write
    float4 tb2a = __ldg((const float4*)(tb2 + tx*8));
    float4 tb2b = __ldg((const float4*)(tb2 + tx*8 + 4));
    #pragma unroll
    for (int r = 0; r < 8; r++){
        size_t row = (size_t)(r0 + ty*8 + r);
        float4 o0, o1;
        o0.x = mishf(lo2(acc[r][0]) + tb2a.x);
        o0.y = mishf(hi2(acc[r][0]) + tb2a.y);
        o0.z = mishf(lo2(acc[r][1]) + tb2a.z);
        o0.w = mishf(hi2(acc[r][1]) + tb2a.w);
        o1.x = mishf(lo2(acc[r][2]) + tb2b.x);
        o1.y = mishf(hi2(acc[r][2]) + tb2b.y);
        o1.z = mishf(lo2(acc[r][3]) + tb2b.z);
        o1.w = mishf(hi2(acc[r][3]) + tb2b.w);
        *(float4*)(g_tbuf + row*256 + tx*8)     = o0;
        *(float4*)(g_tbuf + row*256 + tx*8 + 4) = o1;
    }
}

// ---------------------------------------------------------------------------
// Kernel 2: heads + gates + monotonic MLPs. 256 rows/block, 256 threads.
// Rows bucketed by band; (band, 8-row-group) pairs flattened into one
// work-list so ALL warps stay busy regardless of band distribution.
// Gate branch short-circuits at runtime when sw2/stw2 == 0 (device-checked).
// ---------------------------------------------------------------------------
__global__ __launch_bounds__(256)
void heads_kernel(const float* __restrict__ x,
                  const float* __restrict__ hw1, const float* __restrict__ hb1,
                  const float* __restrict__ hw2, const float* __restrict__ hb2,
                  const float* __restrict__ sw1, const float* __restrict__ sb1,
                  const float* __restrict__ sw2, const float* __restrict__ sb2,
                  const float* __restrict__ stw1, const float* __restrict__ stb1,
                  const float* __restrict__ stw2, const float* __restrict__ stb2,
                  const float* __restrict__ sun_w1, const float* __restrict__ sun_b1,
                  const float* __restrict__ sun_w2, const float* __restrict__ sun_b2,
                  const float* __restrict__ storm_w1, const float* __restrict__ storm_b1,
                  const float* __restrict__ storm_w2, const float* __restrict__ storm_b2,
                  float* __restrict__ out, int B)
{
    __shared__ unsigned short lists[9*256];
    __shared__ int   counts[9];
    __shared__ float partial[256];
    __shared__ float sunw1s[8], sunb1s[8], sunw2s[8];
    __shared__ float stmw1s[8], stmb1s[8], stmw2s[8];
    __shared__ float consts[4];   // sun_b2, storm_b2, sunGate, stormGate
    __shared__ int   zflags[2];
    __shared__ unsigned char  gband[48];
    __shared__ unsigned short goff[48];
    __shared__ int   ngroups;

    const int tid = threadIdx.x;
    const int r0  = blockIdx.x * 256;
    const int row = r0 + tid;

    if (tid < 8){
        sunw1s[tid] = softplusf(sun_w1[tid]);
        sunb1s[tid] = sun_b1[tid];
        sunw2s[tid] = softplusf(sun_w2[tid]);
        stmw1s[tid] = softplusf(storm_w1[tid]);
        stmb1s[tid] = storm_b1[tid];
        stmw2s[tid] = softplusf(storm_w2[tid]);
    }
    if (tid == 0){
        consts[0] = sun_b2[0];
        consts[1] = storm_b2[0];
        int z1 = 1, z2 = 1;
        for (int j = 0; j < 64; j++){
            if (sw2[j]  != 0.f) z1 = 0;
            if (stw2[j] != 0.f) z2 = 0;
        }
        zflags[0] = z1; zflags[1] = z2;
        consts[2] = sigmoidf_(sb2[0]);
        consts[3] = sigmoidf_(stb2[0]);
    }
    if (tid < 9) counts[tid] = 0;
    __syncthreads();

    // per-row scalar path
    float sfi = x[(size_t)row*18 + 15];
    float kp  = x[(size_t)row*18 + 16];
    int band  = (int)x[(size_t)row*18 + 17];
    band = min(max(band, 0), 8);

    float sunv = consts[0], stmv = consts[1];
    #pragma unroll
    for (int j = 0; j < 8; j++){
        sunv = fmaf(tanhf(fmaf(sfi, sunw1s[j], sunb1s[j])), sunw2s[j], sunv);
        stmv = fmaf(tanhf(fmaf(kp,  stmw1s[j], stmb1s[j])), stmw2s[j], stmv);
    }

    float sg, stg;
    if (zflags[0]) sg = consts[2];
    else {  // general (cold) path: correct for arbitrary sw2
        float logit = sb2[0];
        const float* tr = g_tbuf + (size_t)row*256;
        for (int j = 0; j < 64; j++){
            float s = sb1[j];
            for (int d = 0; d < 256; d++) s = fmaf(tr[d], sw1[d*64 + j], s);
            logit = fmaf(mishf(s), sw2[j], logit);
        }
        sg = sigmoidf_(logit);
    }
    if (zflags[1]) stg = consts[3];
    else {
        float logit = stb2[0];
        const float* tr = g_tbuf + (size_t)row*256;
        for (int j = 0; j < 64; j++){
            float s = stb1[j];
            for (int d = 0; d < 256; d++) s = fmaf(tr[d], stw1[d*64 + j], s);
            logit = fmaf(mishf(s), stw2[j], logit);
        }
        stg = sigmoidf_(logit);
    }
    partial[tid] = sg*sunv + stg*stmv;

    int pos = atomicAdd(&counts[band], 1);
    lists[band*256 + pos] = (unsigned short)tid;
    __syncthreads();

    // flatten (band, 8-row-group) pairs into one work-list (<= 41 entries)
    if (tid == 0){
        int n = 0;
        for (int k = 0; k < 9; k++){
            int c = counts[k];
            for (int b = 0; b < c; b += 8){
                gband[n] = (unsigned char)k;
                goff[n]  = (unsigned short)b;
                n++;
            }
        }
        ngroups = n;
    }
    __syncthreads();

    const int lane = tid & 31, wid = tid >> 5;
    const int ng = ngroups;

    for (int gi = wid; gi < ng; gi += 8){
        const int k    = gband[gi];
        const int base = goff[gi];
        const int m    = min(8, counts[k] - base);
        int lr[8];
        #pragma unroll
        for (int j = 0; j < 8; j++)
            lr[j] = lists[k*256 + base + (j < m ? j : m-1)];

        const float* W = hw1 + (size_t)k*32768;   // (256,128) row-major over d

        unsigned long long acc[8][2];
        #pragma unroll
        for (int j = 0; j < 8; j++){ acc[j][0] = 0ull; acc[j][1] = 0ull; }

        for (int d = 0; d < 256; d += 4){
            float4 w0 = __ldg((const float4*)(W + (size_t)(d+0)*128 + lane*4));
            float4 w1 = __ldg((const float4*)(W + (size_t)(d+1)*128 + lane*4));
            float4 w2 = __ldg((const float4*)(W + (size_t)(d+2)*128 + lane*4));
            float4 w3 = __ldg((const float4*)(W + (size_t)(d+3)*128 + lane*4));
            unsigned long long b00 = pack2(w0.x,w0.y), b01 = pack2(w0.z,w0.w);
            unsigned long long b10 = pack2(w1.x,w1.y), b11 = pack2(w1.z,w1.w);
            unsigned long long b20 = pack2(w2.x,w2.y), b21 = pack2(w2.z,w2.w);
            unsigned long long b30 = pack2(w3.x,w3.y), b31 = pack2(w3.z,w3.w);
            #pragma unroll
            for (int j = 0; j < 8; j++){
                float4 tv = __ldg((const float4*)(g_tbuf + (size_t)(r0 + lr[j])*256 + d));
                unsigned long long a0 = pack2(tv.x,tv.x), a1 = pack2(tv.y,tv.y);
                unsigned long long a2 = pack2(tv.z,tv.z), a3 = pack2(tv.w,tv.w);
                fma2(acc[j][0], a0, b00); fma2(acc[j][1], a0, b01);
                fma2(acc[j][0], a1, b10); fma2(acc[j][1], a1, b11);
                fma2(acc[j][0], a2, b20); fma2(acc[j][1], a2, b21);
                fma2(acc[j][0], a3, b30); fma2(acc[j][1], a3, b31);
            }
        }

        const int c0 = lane*4;
        float4 hb1v = __ldg((const float4*)(hb1 + k*128 + c0));
        float4 hw2v = __ldg((const float4*)(hw2 + k*128 + c0));
        float hb2k  = __ldg(&hb2[k]);
        #pragma unroll
        for (int j = 0; j < 8; j++){
            float s = mishf(lo2(acc[j][0]) + hb1v.x) * hw2v.x
                    + mishf(hi2(acc[j][0]) + hb1v.y) * hw2v.y
                    + mishf(lo2(acc[j][1]) + hb1v.z) * hw2v.z
                    + mishf(hi2(acc[j][1]) + hb1v.w) * hw2v.w;
            #pragma unroll
            for (int o = 16; o > 0; o >>= 1)
                s += __shfl_down_sync(0xffffffffu, s, o);
            if (lane == 0 && j < m)
                out[r0 + lr[j]] = s + hb2k + partial[lr[j]];
        }
    }
}

// ---------------------------------------------------------------------------
extern "C" void kernel_launch(void* const* d_in, const int* in_sizes, int n_in,
                              void* d_out, int out_size)
{
    const float* x       = (const float*)d_in[0];
    const float* tw1     = (const float*)d_in[1];
    const float* tb1     = (const float*)d_in[2];
    const float* tw2     = (const float*)d_in[3];
    const float* tb2     = (const float*)d_in[4];
    const float* hw1     = (const float*)d_in[5];
    const float* hb1     = (const float*)d_in[6];
    const float* hw2     = (const float*)d_in[7];
    const float* hb2     = (const float*)d_in[8];
    const float* sw1     = (const float*)d_in[9];
    const float* sb1     = (const float*)d_in[10];
    const float* sw2     = (const float*)d_in[11];
    const float* sb2     = (const float*)d_in[12];
    const float* stw1    = (const float*)d_in[13];
    const float* stb1    = (const float*)d_in[14];
    const float* stw2    = (const float*)d_in[15];
    const float* stb2    = (const float*)d_in[16];
    const float* sun_w1  = (const float*)d_in[17];
    const float* sun_b1  = (const float*)d_in[18];
    const float* sun_w2  = (const float*)d_in[19];
    const float* sun_b2  = (const float*)d_in[20];
    const float* storm_w1= (const float*)d_in[21];
    const float* storm_b1= (const float*)d_in[22];
    const float* storm_w2= (const float*)d_in[23];
    const float* storm_b2= (const float*)d_in[24];
    float* out = (float*)d_out;

    int B = in_sizes[0] / 18;

    size_t smem1 = (size_t)(64*512 + 2*8192 + 64*16) * sizeof(float);  // 196KB
    cudaFuncSetAttribute(trunk_kernel,
                         cudaFuncAttributeMaxDynamicSharedMemorySize, (int)smem1);

    trunk_kernel<<<B/64, 256, smem1>>>(x, tw1, tb1, tw2, tb2, B);
    heads_kernel<<<B/256, 256>>>(x, hw1, hb1, hw2, hb2,
                                 sw1, sb1, sw2, sb2,
                                 stw1, stb1, stw2, stb2,
                                 sun_w1, sun_b1, sun_w2, sun_b2,
                                 storm_w1, storm_b1, storm_w2, storm_b2,
                                 out, B);
}

// round 5
// speedup vs baseline: 1.7829x; 1.1584x over previous
#include <cuda_runtime.h>
#include <cstdint>

// ---------------------------------------------------------------------------
// IonisGateV26: fused gated MLP.
//  K1 trunk: t = mish(mish(x@tw1+tb1)@tw2+tb2) -> g_tbuf.
//     512 threads, h1 stored TRANSPOSED so LDS.64 yields (row r, row r+1)
//     pairs for f32x2 accumulators (no pack2(a,a) MOVs). cp.async
//     double-buffered tw2 chunks.
//  K2 heads: band-bucketed rows, flattened (band,group) work-list; 2 blocks/SM.
// ---------------------------------------------------------------------------

#define B_MAX 262144
__device__ float g_tbuf[(size_t)B_MAX * 256];   // t scratch, 256MB

// ---------------- math helpers ----------------
__device__ __forceinline__ float mishf(float v){
    if (v > 20.f) return v;
    float e = __expf(v);
    float n = e * (e + 2.f);
    return v * __fdividef(n, n + 2.f);
}
__device__ __forceinline__ float softplusf(float v){
    if (v > 20.f) return v;
    return log1pf(__expf(v));
}
__device__ __forceinline__ float sigmoidf_(float v){
    return __fdividef(1.f, 1.f + __expf(-v));
}

// ---------------- packed f32x2 helpers ----------------
__device__ __forceinline__ unsigned long long pack2(float a, float b){
    unsigned long long r;
    asm("mov.b64 %0, {%1, %2};" : "=l"(r)
        : "r"(__float_as_uint(a)), "r"(__float_as_uint(b)));
    return r;
}
__device__ __forceinline__ void fma2(unsigned long long &d,
                                     unsigned long long a, unsigned long long b){
    asm("fma.rn.f32x2 %0, %1, %2, %0;" : "+l"(d) : "l"(a), "l"(b));
}
__device__ __forceinline__ float lo2(unsigned long long v){
    return __uint_as_float((unsigned)(v & 0xffffffffull));
}
__device__ __forceinline__ float hi2(unsigned long long v){
    return __uint_as_float((unsigned)(v >> 32));
}

// ---------------- cp.async helpers ----------------
__device__ __forceinline__ unsigned smem_u32(const void* p){
    unsigned a;
    asm("{ .reg .u64 t; cvta.to.shared.u64 t, %1; cvt.u32.u64 %0, t; }"
        : "=r"(a) : "l"(p));
    return a;
}
__device__ __forceinline__ void cp16(unsigned s, const void* g){
    asm volatile("cp.async.cg.shared.global [%0], [%1], 16;\n" :: "r"(s), "l"(g));
}
__device__ __forceinline__ void cp_commit(){
    asm volatile("cp.async.commit_group;\n" ::: "memory");
}
template<int N> __device__ __forceinline__ void cp_wait(){
    asm volatile("cp.async.wait_group %0;\n" :: "n"(N) : "memory");
}

// ---------------------------------------------------------------------------
// Kernel 1: trunk. 64 rows/block, 512 threads, 1 block/SM (16 warps).
// smem: h1T (512 k x 64 rows, 128KB) | buf0,buf1 (2 x 8192 f32 = 64KB)
//       | xs (64x17 padded, 4.25KB)  => ~196.3KB.
// GEMM2: C(64x256) = h1(64x512) @ tw2(512x256).
// Thread (rg=tid>>6, cg=tid&63): rows rg*8..+7 (as 4 row-PAIRS), cols cg*4..+3.
// acc[i][c] is f32x2 over (row 2*(rg*4+i), row 2*(rg*4+i)+1) at col cg*4+c.
// A operand = LDS.64 from transposed h1 (natural row pair, warp-broadcast);
// B operand = LDS.128 (4 cols) duplicated into 4 f32x2 regs.
// ---------------------------------------------------------------------------
__global__ __launch_bounds__(512, 1)
void trunk_kernel(const float* __restrict__ x,
                  const float* __restrict__ tw1, const float* __restrict__ tb1,
                  const float* __restrict__ tw2, const float* __restrict__ tb2,
                  int B)
{
    extern __shared__ float sm[];
    float* h1T  = sm;               // [512][64]
    float* buf0 = sm + 512*64;      // 8192
    float* buf1 = buf0 + 8192;      // 8192
    float* xs   = buf1 + 8192;      // [64][17]
    const int tid = threadIdx.x;
    const int r0  = blockIdx.x * 64;

    // stage x_deep (64 x 15, padded stride 17) and tw1 (15x512, into buf0)
    for (int i = tid; i < 64*15; i += 512){
        int r = i / 15, c = i - r*15;
        xs[r*17 + c] = x[(size_t)(r0 + r)*18 + c];
    }
    for (int i = tid; i < 15*512; i += 512) buf0[i] = __ldg(&tw1[i]);
    __syncthreads();

    // GEMM1 (K=15) + mish -> h1T[c][r]  (transposed store, conflict-free)
    for (int idx = tid; idx < 64*512; idx += 512){
        int r = idx & 63, c = idx >> 6;
        float acc = __ldg(&tb1[c]);
        #pragma unroll
        for (int d = 0; d < 15; d++)
            acc = fmaf(xs[r*17 + d], buf0[d*512 + c], acc);
        h1T[c*64 + r] = mishf(acc);
    }
    __syncthreads();   // buf0 reads done; safe to overwrite with tw2 chunk 0

    const int cg = tid & 63;        // col group: cols cg*4..cg*4+3
    const int rg = tid >> 6;        // row group: rows rg*8..rg*8+7

    unsigned long long acc[4][4];   // [row-pair][col]
    #pragma unroll
    for (int i = 0; i < 4; i++)
        #pragma unroll
        for (int c = 0; c < 4; c++) acc[i][c] = 0ull;

    // chunk copy: 32 k-rows x 256 cols = 8192 floats = 2048 x 16B, 4/thread
    const unsigned b0a = smem_u32(buf0), b1a = smem_u32(buf1);
    auto issue_chunk = [&](int c){
        unsigned dst = (c & 1) ? b1a : b0a;
        const float* src = tw2 + (size_t)c * 32 * 256;
        #pragma unroll
        for (int i = 0; i < 4; i++){
            int e = tid + i * 512;             // float4 index
            cp16(dst + e * 16, src + e * 4);
        }
        cp_commit();
    };

    issue_chunk(0);
    #pragma unroll 1
    for (int c = 0; c < 16; c++){
        if (c + 1 < 16) issue_chunk(c + 1);
        if (c + 1 < 16) cp_wait<1>(); else cp_wait<0>();
        __syncthreads();                        // current chunk visible
        const float4* wb4 = (const float4*)((c & 1) ? buf1 : buf0);
        const float2* aT  = (const float2*)(h1T + (c * 32) * 64);
        #pragma unroll 4
        for (int kk = 0; kk < 32; kk++){
            float4 b = wb4[kk*64 + cg];
            unsigned long long p0 = pack2(b.x, b.x), p1 = pack2(b.y, b.y);
            unsigned long long p2 = pack2(b.z, b.z), p3 = pack2(b.w, b.w);
            const float2* arow = aT + kk*32 + rg*4;   // row pairs (broadcast)
            #pragma unroll
            for (int i = 0; i < 4; i++){
                float2 ap = arow[i];
                unsigned long long a2 = pack2(ap.x, ap.y);
                fma2(acc[i][0], a2, p0); fma2(acc[i][1], a2, p1);
                fma2(acc[i][2], a2, p2); fma2(acc[i][3], a2, p3);
            }
        }
        __syncthreads();   // reads of this buffer done before refill
    }

    // epilogue: + tb2, mish, coalesced STG.128 (two rows per row-pair)
    float4 tb2v = __ldg((const float4*)(tb2 + cg*4));
    #pragma unroll
    for (int i = 0; i < 4; i++){
        int rowe = r0 + rg*8 + i*2;
        float4 e0, e1;
        e0.x = mishf(lo2(acc[i][0]) + tb2v.x);
        e0.y = mishf(lo2(acc[i][1]) + tb2v.y);
        e0.z = mishf(lo2(acc[i][2]) + tb2v.z);
        e0.w = mishf(lo2(acc[i][3]) + tb2v.w);
        e1.x = mishf(hi2(acc[i][0]) + tb2v.x);
        e1.y = mishf(hi2(acc[i][1]) + tb2v.y);
        e1.z = mishf(hi2(acc[i][2]) + tb2v.z);
        e1.w = mishf(hi2(acc[i][3]) + tb2v.w);
        *(float4*)(g_tbuf + (size_t)rowe*256     + cg*4) = e0;
        *(float4*)(g_tbuf + (size_t)(rowe+1)*256 + cg*4) = e1;
    }
}

// ---------------------------------------------------------------------------
// Kernel 2: heads + gates + monotonic MLPs. 256 rows/block, 256 threads,
// __launch_bounds__(256,2) -> <=128 regs -> 2 blocks/SM (16 warps).
// Rows bucketed by band; flattened (band, 8-row-group) work-list.
// ---------------------------------------------------------------------------
__global__ __launch_bounds__(256, 2)
void heads_kernel(const float* __restrict__ x,
                  const float* __restrict__ hw1, const float* __restrict__ hb1,
                  const float* __restrict__ hw2, const float* __restrict__ hb2,
                  const float* __restrict__ sw1, const float* __restrict__ sb1,
                  const float* __restrict__ sw2, const float* __restrict__ sb2,
                  const float* __restrict__ stw1, const float* __restrict__ stb1,
                  const float* __restrict__ stw2, const float* __restrict__ stb2,
                  const float* __restrict__ sun_w1, const float* __restrict__ sun_b1,
                  const float* __restrict__ sun_w2, const float* __restrict__ sun_b2,
                  const float* __restrict__ storm_w1, const float* __restrict__ storm_b1,
                  const float* __restrict__ storm_w2, const float* __restrict__ storm_b2,
                  float* __restrict__ out, int B)
{
    __shared__ unsigned short lists[9*256];
    __shared__ int   counts[9];
    __shared__ float partial[256];
    __shared__ float sunw1s[8], sunb1s[8], sunw2s[8];
    __shared__ float stmw1s[8], stmb1s[8], stmw2s[8];
    __shared__ float consts[4];
    __shared__ int   zflags[2];
    __shared__ unsigned char  gband[48];
    __shared__ unsigned short goff[48];
    __shared__ int   ngroups;

    const int tid = threadIdx.x;
    const int r0  = blockIdx.x * 256;
    const int row = r0 + tid;

    if (tid < 8){
        sunw1s[tid] = softplusf(sun_w1[tid]);
        sunb1s[tid] = sun_b1[tid];
        sunw2s[tid] = softplusf(sun_w2[tid]);
        stmw1s[tid] = softplusf(storm_w1[tid]);
        stmb1s[tid] = storm_b1[tid];
        stmw2s[tid] = softplusf(storm_w2[tid]);
    }
    if (tid == 0){
        consts[0] = sun_b2[0];
        consts[1] = storm_b2[0];
        int z1 = 1, z2 = 1;
        for (int j = 0; j < 64; j++){
            if (sw2[j]  != 0.f) z1 = 0;
            if (stw2[j] != 0.f) z2 = 0;
        }
        zflags[0] = z1; zflags[1] = z2;
        consts[2] = sigmoidf_(sb2[0]);
        consts[3] = sigmoidf_(stb2[0]);
    }
    if (tid < 9) counts[tid] = 0;
    __syncthreads();

    // per-row scalar path
    float sfi = x[(size_t)row*18 + 15];
    float kp  = x[(size_t)row*18 + 16];
    int band  = (int)x[(size_t)row*18 + 17];
    band = min(max(band, 0), 8);

    float sunv = consts[0], stmv = consts[1];
    #pragma unroll
    for (int j = 0; j < 8; j++){
        sunv = fmaf(tanhf(fmaf(sfi, sunw1s[j], sunb1s[j])), sunw2s[j], sunv);
        stmv = fmaf(tanhf(fmaf(kp,  stmw1s[j], stmb1s[j])), stmw2s[j], stmv);
    }

    float sg, stg;
    if (zflags[0]) sg = consts[2];
    else {  // general (cold) path: correct for arbitrary sw2
        float logit = sb2[0];
        const float* tr = g_tbuf + (size_t)row*256;
        for (int j = 0; j < 64; j++){
            float s = sb1[j];
            for (int d = 0; d < 256; d++) s = fmaf(tr[d], sw1[d*64 + j], s);
            logit = fmaf(mishf(s), sw2[j], logit);
        }
        sg = sigmoidf_(logit);
    }
    if (zflags[1]) stg = consts[3];
    else {
        float logit = stb2[0];
        const float* tr = g_tbuf + (size_t)row*256;
        for (int j = 0; j < 64; j++){
            float s = stb1[j];
            for (int d = 0; d < 256; d++) s = fmaf(tr[d], stw1[d*64 + j], s);
            logit = fmaf(mishf(s), stw2[j], logit);
        }
        stg = sigmoidf_(logit);
    }
    partial[tid] = sg*sunv + stg*stmv;

    int pos = atomicAdd(&counts[band], 1);
    lists[band*256 + pos] = (unsigned short)tid;
    __syncthreads();

    // flatten (band, 8-row-group) pairs into one work-list (<= 41 entries)
    if (tid == 0){
        int n = 0;
        for (int k = 0; k < 9; k++){
            int c = counts[k];
            for (int b = 0; b < c; b += 8){
                gband[n] = (unsigned char)k;
                goff[n]  = (unsigned short)b;
                n++;
            }
        }
        ngroups = n;
    }
    __syncthreads();

    const int lane = tid & 31, wid = tid >> 5;
    const int ng = ngroups;

    for (int gi = wid; gi < ng; gi += 8){
        const int k    = gband[gi];
        const int base = goff[gi];
        const int m    = min(8, counts[k] - base);
        int lr[8];
        #pragma unroll
        for (int j = 0; j < 8; j++)
            lr[j] = lists[k*256 + base + (j < m ? j : m-1)];

        const float* W = hw1 + (size_t)k*32768;   // (256,128) row-major over d

        unsigned long long acc[8][2];
        #pragma unroll
        for (int j = 0; j < 8; j++){ acc[j][0] = 0ull; acc[j][1] = 0ull; }

        for (int d = 0; d < 256; d += 4){
            float4 w0 = __ldg((const float4*)(W + (size_t)(d+0)*128 + lane*4));
            float4 w1 = __ldg((const float4*)(W + (size_t)(d+1)*128 + lane*4));
            float4 w2 = __ldg((const float4*)(W + (size_t)(d+2)*128 + lane*4));
            float4 w3 = __ldg((const float4*)(W + (size_t)(d+3)*128 + lane*4));
            unsigned long long b00 = pack2(w0.x,w0.y), b01 = pack2(w0.z,w0.w);
            unsigned long long b10 = pack2(w1.x,w1.y), b11 = pack2(w1.z,w1.w);
            unsigned long long b20 = pack2(w2.x,w2.y), b21 = pack2(w2.z,w2.w);
            unsigned long long b30 = pack2(w3.x,w3.y), b31 = pack2(w3.z,w3.w);
            #pragma unroll
            for (int j = 0; j < 8; j++){
                float4 tv = __ldg((const float4*)(g_tbuf + (size_t)(r0 + lr[j])*256 + d));
                unsigned long long a0 = pack2(tv.x,tv.x), a1 = pack2(tv.y,tv.y);
                unsigned long long a2 = pack2(tv.z,tv.z), a3 = pack2(tv.w,tv.w);
                fma2(acc[j][0], a0, b00); fma2(acc[j][1], a0, b01);
                fma2(acc[j][0], a1, b10); fma2(acc[j][1], a1, b11);
                fma2(acc[j][0], a2, b20); fma2(acc[j][1], a2, b21);
                fma2(acc[j][0], a3, b30); fma2(acc[j][1], a3, b31);
            }
        }

        const int c0 = lane*4;
        float4 hb1v = __ldg((const float4*)(hb1 + k*128 + c0));
        float4 hw2v = __ldg((const float4*)(hw2 + k*128 + c0));
        float hb2k  = __ldg(&hb2[k]);
        #pragma unroll
        for (int j = 0; j < 8; j++){
            float s = mishf(lo2(acc[j][0]) + hb1v.x) * hw2v.x
                    + mishf(hi2(acc[j][0]) + hb1v.y) * hw2v.y
                    + mishf(lo2(acc[j][1]) + hb1v.z) * hw2v.z
                    + mishf(hi2(acc[j][1]) + hb1v.w) * hw2v.w;
            #pragma unroll
            for (int o = 16; o > 0; o >>= 1)
                s += __shfl_down_sync(0xffffffffu, s, o);
            if (lane == 0 && j < m)
                out[r0 + lr[j]] = s + hb2k + partial[lr[j]];
        }
    }
}

// ---------------------------------------------------------------------------
extern "C" void kernel_launch(void* const* d_in, const int* in_sizes, int n_in,
                              void* d_out, int out_size)
{
    const float* x       = (const float*)d_in[0];
    const float* tw1     = (const float*)d_in[1];
    const float* tb1     = (const float*)d_in[2];
    const float* tw2     = (const float*)d_in[3];
    const float* tb2     = (const float*)d_in[4];
    const float* hw1     = (const float*)d_in[5];
    const float* hb1     = (const float*)d_in[6];
    const float* hw2     = (const float*)d_in[7];
    const float* hb2     = (const float*)d_in[8];
    const float* sw1     = (const float*)d_in[9];
    const float* sb1     = (const float*)d_in[10];
    const float* sw2     = (const float*)d_in[11];
    const float* sb2     = (const float*)d_in[12];
    const float* stw1    = (const float*)d_in[13];
    const float* stb1    = (const float*)d_in[14];
    const float* stw2    = (const float*)d_in[15];
    const float* stb2    = (const float*)d_in[16];
    const float* sun_w1  = (const float*)d_in[17];
    const float* sun_b1  = (const float*)d_in[18];
    const float* sun_w2  = (const float*)d_in[19];
    const float* sun_b2  = (const float*)d_in[20];
    const float* storm_w1= (const float*)d_in[21];
    const float* storm_b1= (const float*)d_in[22];
    const float* storm_w2= (const float*)d_in[23];
    const float* storm_b2= (const float*)d_in[24];
    float* out = (float*)d_out;

    int B = in_sizes[0] / 18;

    size_t smem1 = (size_t)(512*64 + 2*8192 + 64*17) * sizeof(float);  // ~196.3KB
    cudaFuncSetAttribute(trunk_kernel,
                         cudaFuncAttributeMaxDynamicSharedMemorySize, (int)smem1);

    trunk_kernel<<<B/64, 512, smem1>>>(x, tw1, tb1, tw2, tb2, B);
    heads_kernel<<<B/256, 256>>>(x, hw1, hb1, hw2, hb2,
                                 sw1, sb1, sw2, sb2,
                                 stw1, stb1, stw2, stb2,
                                 sun_w1, sun_b1, sun_w2, sun_b2,
                                 storm_w1, storm_b1, storm_w2, storm_b2,
                                 out, B);
}

// round 9
// speedup vs baseline: 2.6685x; 1.4967x over previous
#include <cuda_runtime.h>
#include <cuda_bf16.h>
#include <cstdint>

// ---------------------------------------------------------------------------
// IonisGateV26: fused gated MLP.
//  K0 prep : tw2 (512x256 f32) -> bf16 hi/lo "fragment-linear" images in gmem
//            (32 k16-chunks x 16KB; each chunk: hi 8KB | lo 8KB, laid out so a
//            lane's mma.m16n8k16 B-regs {b0,b1} sit at lane*8B).
//  K1 trunk: t = mish(mish(x@tw1+tb1)@tw2+tb2) -> g_tbuf.
//            GEMM2 on mma.sync bf16 (baseline PTX, no sm_103a features),
//            3-term hi/lo split, fragment-linear smem, cp.async 4-deep ring.
//  K2 heads: band-bucketed rows, flattened work-list (unchanged fp32 f32x2).
// ---------------------------------------------------------------------------

#define B_MAX 262144
__device__ float g_tbuf[(size_t)B_MAX * 256];            // t scratch, 256MB
__device__ __align__(16) unsigned char g_bw[32 * 16384]; // tw2 frag images 512KB

// ---------------- math helpers ----------------
__device__ __forceinline__ float mishf(float v){
    if (v > 20.f) return v;
    float e = __expf(v);
    float n = e * (e + 2.f);
    return v * __fdividef(n, n + 2.f);
}
__device__ __forceinline__ float softplusf(float v){
    if (v > 20.f) return v;
    return log1pf(__expf(v));
}
__device__ __forceinline__ float sigmoidf_(float v){
    return __fdividef(1.f, 1.f + __expf(-v));
}

// ---------------- packed f32x2 helpers (heads kernel) ----------------
__device__ __forceinline__ unsigned long long pack2(float a, float b){
    unsigned long long r;
    asm("mov.b64 %0, {%1, %2};" : "=l"(r)
        : "r"(__float_as_uint(a)), "r"(__float_as_uint(b)));
    return r;
}
__device__ __forceinline__ void fma2(unsigned long long &d,
                                     unsigned long long a, unsigned long long b){
    asm("fma.rn.f32x2 %0, %1, %2, %0;" : "+l"(d) : "l"(a), "l"(b));
}
__device__ __forceinline__ float lo2(unsigned long long v){
    return __uint_as_float((unsigned)(v & 0xffffffffull));
}
__device__ __forceinline__ float hi2(unsigned long long v){
    return __uint_as_float((unsigned)(v >> 32));
}

// ---------------- cp.async helpers ----------------
__device__ __forceinline__ unsigned smem_u32(const void* p){
    unsigned a;
    asm("{ .reg .u64 t; cvta.to.shared.u64 t, %1; cvt.u32.u64 %0, t; }"
        : "=r"(a) : "l"(p));
    return a;
}
__device__ __forceinline__ void cp16(unsigned s, const void* g){
    asm volatile("cp.async.cg.shared.global [%0], [%1], 16;\n" :: "r"(s), "l"(g));
}
__device__ __forceinline__ void cp_commit(){
    asm volatile("cp.async.commit_group;\n" ::: "memory");
}
template<int N> __device__ __forceinline__ void cp_wait(){
    asm volatile("cp.async.wait_group %0;\n" :: "n"(N) : "memory");
}

// ---------------- mma.sync bf16 (baseline PTX, sm_80+) ----------------
__device__ __forceinline__ void mma16816(float* c, const uint4& a, const uint2& b){
    asm("mma.sync.aligned.m16n8k16.row.col.f32.bf16.bf16.f32 "
        "{%0,%1,%2,%3}, {%4,%5,%6,%7}, {%8,%9}, {%0,%1,%2,%3};"
        : "+f"(c[0]), "+f"(c[1]), "+f"(c[2]), "+f"(c[3])
        : "r"(a.x), "r"(a.y), "r"(a.z), "r"(a.w), "r"(b.x), "r"(b.y));
}
__device__ __forceinline__ unsigned packbf(float x, float y){
    __nv_bfloat162 t = __floats2bfloat162_rn(x, y);
    return *(unsigned*)&t;
}

// ---------------------------------------------------------------------------
// Kernel 0: prep tw2 -> fragment-linear bf16 hi/lo images.
// Element (k,n): ktile=k>>4, ntile=n>>3; lane=(n&7)*4+((k&7)>>1);
// reg=(k>>3)&1; byte=(k&1)*2.
// addr = ktile*16384 + [hi:0|lo:8192] + ntile*256 + lane*8 + reg*4 + byte.
// ---------------------------------------------------------------------------
__global__ void prep_tw2_kernel(const float* __restrict__ tw2){
    int idx = blockIdx.x * blockDim.x + threadIdx.x;   // 0..131071
    int k = idx >> 8, n = idx & 255;
    float v = tw2[(size_t)k * 256 + n];
    __nv_bfloat16 hi = __float2bfloat16(v);
    __nv_bfloat16 lo = __float2bfloat16(v - __bfloat162float(hi));
    int kr = k & 15;
    unsigned lane = (unsigned)((n & 7) * 4 + ((kr & 7) >> 1));
    unsigned off  = (unsigned)((k >> 4) * 16384 + (n >> 3) * 256
                    + lane * 8 + ((kr >> 3) & 1) * 4 + (kr & 1) * 2);
    *(__nv_bfloat16*)(g_bw + off)        = hi;
    *(__nv_bfloat16*)(g_bw + off + 8192) = lo;
}

// ---------------------------------------------------------------------------
// Kernel 1: trunk. 64 rows/block, 256 threads (8 warps), 1 block/SM.
// smem: [0:65536) A-hi frags | [65536:131072) A-lo frags
//       [131072:196608) B ring 4 x 16KB chunks (hi 8KB | lo 8KB each)
//       [196608:227328) tw1s (15x512 f32)
// A frag addr: ((ktile*4 + mtile)*32 + lane)*16 + reg*4   (reg = a0..a3)
// Warp (wm=w>>2, wn=w&3): mtiles wm*2..+1 (32 rows), ntiles wn*8..+7 (64 cols).
// ---------------------------------------------------------------------------
__global__ __launch_bounds__(256, 1)
void trunk_kernel(const float* __restrict__ x,
                  const float* __restrict__ tw1, const float* __restrict__ tb1,
                  const float* __restrict__ tb2, int B)
{
    extern __shared__ __align__(16) unsigned char smem[];
    const unsigned sbase = smem_u32(smem);
    const unsigned OFF_AH = 0, OFF_AL = 65536, OFF_B = 131072, OFF_TW1 = 196608;
    float* tw1s = (float*)(smem + OFF_TW1);

    const int tid = threadIdx.x;
    const int w   = tid >> 5;
    const int l   = tid & 31;
    const int r0  = blockIdx.x * 64;

    // issue B chunks 0..2 (overlap with GEMM1)
    #pragma unroll
    for (int p = 0; p < 3; p++){
        unsigned dst = sbase + OFF_B + p * 16384;
        const unsigned char* src = g_bw + p * 16384;
        #pragma unroll
        for (int i = 0; i < 4; i++){
            int e = tid + i * 256;
            cp16(dst + e * 16, src + e * 16);
        }
        cp_commit();
    }

    // stage tw1 (15x512 f32)
    for (int i = tid; i < 7680; i += 256) tw1s[i] = __ldg(&tw1[i]);
    __syncthreads();

    // ---- GEMM1 (K=15) + mish + hi/lo split -> A frags ----
    // Warp w owns mtile mt = w&3 and ktile half kth = (w>>2)*16.
    // Thread owns frag lane l: rows m0 = mt*16 + (l>>2), m1 = m0+8;
    // cols per ktile KT: c0 = KT*16 + (l&3)*2 (pairs c0,c0+1 and c0+8,c0+9).
    {
        const int mt  = w & 3;
        const int kth = (w >> 2) * 16;
        const int m0  = mt * 16 + (l >> 2);
        const int m1  = m0 + 8;
        float xr0[15], xr1[15];
        #pragma unroll
        for (int d = 0; d < 15; d++){
            xr0[d] = __ldg(&x[(size_t)(r0 + m0) * 18 + d]);
            xr1[d] = __ldg(&x[(size_t)(r0 + m1) * 18 + d]);
        }
        #pragma unroll 1
        for (int kt = 0; kt < 16; kt++){
            const int KT = kth + kt;
            const int c0 = KT * 16 + (l & 3) * 2;
            float a00 = __ldg(&tb1[c0]),     a01 = __ldg(&tb1[c0 + 1]);
            float a02 = __ldg(&tb1[c0 + 8]), a03 = __ldg(&tb1[c0 + 9]);
            float a10 = a00, a11 = a01, a12 = a02, a13 = a03;
            #pragma unroll
            for (int d = 0; d < 15; d++){
                float2 wa = *(const float2*)(tw1s + d * 512 + c0);
                float2 wb = *(const float2*)(tw1s + d * 512 + c0 + 8);
                a00 = fmaf(xr0[d], wa.x, a00); a01 = fmaf(xr0[d], wa.y, a01);
                a02 = fmaf(xr0[d], wb.x, a02); a03 = fmaf(xr0[d], wb.y, a03);
                a10 = fmaf(xr1[d], wa.x, a10); a11 = fmaf(xr1[d], wa.y, a11);
                a12 = fmaf(xr1[d], wb.x, a12); a13 = fmaf(xr1[d], wb.y, a13);
            }
            a00 = mishf(a00); a01 = mishf(a01); a02 = mishf(a02); a03 = mishf(a03);
            a10 = mishf(a10); a11 = mishf(a11); a12 = mishf(a12); a13 = mishf(a13);
            // hi parts
            uint4 hv;
            hv.x = packbf(a00, a01);   // a0: row m0, cols c0,c0+1
            hv.y = packbf(a10, a11);   // a1: row m1
            hv.z = packbf(a02, a03);   // a2: row m0, cols +8
            hv.w = packbf(a12, a13);   // a3: row m1, cols +8
            // lo parts (residuals)
            float r00 = a00 - __bfloat162float(__float2bfloat16(a00));
            float r01 = a01 - __bfloat162float(__float2bfloat16(a01));
            float r02 = a02 - __bfloat162float(__float2bfloat16(a02));
            float r03 = a03 - __bfloat162float(__float2bfloat16(a03));
            float r10 = a10 - __bfloat162float(__float2bfloat16(a10));
            float r11 = a11 - __bfloat162float(__float2bfloat16(a11));
            float r12 = a12 - __bfloat162float(__float2bfloat16(a12));
            float r13 = a13 - __bfloat162float(__float2bfloat16(a13));
            uint4 lv;
            lv.x = packbf(r00, r01); lv.y = packbf(r10, r11);
            lv.z = packbf(r02, r03); lv.w = packbf(r12, r13);
            unsigned fa = (unsigned)(((KT * 4 + mt) * 32 + l) * 16);
            *(uint4*)(smem + OFF_AH + fa) = hv;
            *(uint4*)(smem + OFF_AL + fa) = lv;
        }
    }
    __syncthreads();   // A frags visible to all warps

    // ---- GEMM2 main loop: 32 k16 chunks, mma.sync bf16, 3 terms ----
    const int wm = w >> 2;      // 0..1 : mtiles wm*2, wm*2+1
    const int wn = w & 3;       // 0..3 : ntiles wn*8 .. +7
    float acc[2][8][4];
    #pragma unroll
    for (int i = 0; i < 2; i++)
        #pragma unroll
        for (int j = 0; j < 8; j++)
            #pragma unroll
            for (int q = 0; q < 4; q++) acc[i][j][q] = 0.f;

    #pragma unroll 1
    for (int kt = 0; kt < 32; kt++){
        // graduated tail waits: guarantee chunk kt is resident even when no
        // more groups are being committed (kt=30: 2 pending; kt=31: 1 pending)
        if (kt <= 29)      cp_wait<2>();
        else if (kt == 30) cp_wait<1>();
        else               cp_wait<0>();
        __syncthreads();         // all warps done with the buffer being refilled
        if (kt + 3 < 32){        // refill freed buffer with chunk kt+3
            int p = kt + 3;
            unsigned dst = sbase + OFF_B + (p & 3) * 16384;
            const unsigned char* src = g_bw + p * 16384;
            #pragma unroll
            for (int i = 0; i < 4; i++){
                int e = tid + i * 256;
                cp16(dst + e * 16, src + e * 16);
            }
            cp_commit();
        }

        // A fragments (conflict-free LDS.128 at lane*16)
        uint4 ah[2], al[2];
        #pragma unroll
        for (int mt2 = 0; mt2 < 2; mt2++){
            unsigned fa = (unsigned)(((kt * 4 + wm * 2 + mt2) * 32 + l) * 16);
            ah[mt2] = *(const uint4*)(smem + OFF_AH + fa);
            al[mt2] = *(const uint4*)(smem + OFF_AL + fa);
        }
        // B fragments (conflict-free LDS.64 at lane*8)
        const unsigned bb = OFF_B + (unsigned)((kt & 3) * 16384);
        uint2 bh[8], bl[8];
        #pragma unroll
        for (int nt = 0; nt < 8; nt++){
            unsigned fb = bb + (unsigned)(((wn * 8 + nt) * 32 + l) * 8);
            bh[nt] = *(const uint2*)(smem + fb);
            bl[nt] = *(const uint2*)(smem + fb + 8192);
        }
        // term 1: Ahi * Bhi
        #pragma unroll
        for (int mt2 = 0; mt2 < 2; mt2++)
            #pragma unroll
            for (int nt = 0; nt < 8; nt++)
                mma16816(acc[mt2][nt], ah[mt2], bh[nt]);
        // term 2: Ahi * Blo
        #pragma unroll
        for (int mt2 = 0; mt2 < 2; mt2++)
            #pragma unroll
            for (int nt = 0; nt < 8; nt++)
                mma16816(acc[mt2][nt], ah[mt2], bl[nt]);
        // term 3: Alo * Bhi
        #pragma unroll
        for (int mt2 = 0; mt2 < 2; mt2++)
            #pragma unroll
            for (int nt = 0; nt < 8; nt++)
                mma16816(acc[mt2][nt], al[mt2], bh[nt]);
    }

    // ---- epilogue: +tb2, mish, store t (float2 per row-pair) ----
    #pragma unroll
    for (int mt2 = 0; mt2 < 2; mt2++){
        const int rowa = r0 + wm * 32 + mt2 * 16 + (l >> 2);
        const int rowb = rowa + 8;
        #pragma unroll
        for (int nt = 0; nt < 8; nt++){
            const int col = wn * 64 + nt * 8 + (l & 3) * 2;
            float t0 = __ldg(&tb2[col]), t1 = __ldg(&tb2[col + 1]);
            float2 e0, e1;
            e0.x = mishf(acc[mt2][nt][0] + t0);
            e0.y = mishf(acc[mt2][nt][1] + t1);
            e1.x = mishf(acc[mt2][nt][2] + t0);
            e1.y = mishf(acc[mt2][nt][3] + t1);
            *(float2*)(g_tbuf + (size_t)rowa * 256 + col) = e0;
            *(float2*)(g_tbuf + (size_t)rowb * 256 + col) = e1;
        }
    }
}

// ---------------------------------------------------------------------------
// Kernel 2: heads + gates + monotonic MLPs (unchanged from R5 pass).
// ---------------------------------------------------------------------------
__global__ __launch_bounds__(256, 2)
void heads_kernel(const float* __restrict__ x,
                  const float* __restrict__ hw1, const float* __restrict__ hb1,
                  const float* __restrict__ hw2, const float* __restrict__ hb2,
                  const float* __restrict__ sw1, const float* __restrict__ sb1,
                  const float* __restrict__ sw2, const float* __restrict__ sb2,
                  const float* __restrict__ stw1, const float* __restrict__ stb1,
                  const float* __restrict__ stw2, const float* __restrict__ stb2,
                  const float* __restrict__ sun_w1, const float* __restrict__ sun_b1,
                  const float* __restrict__ sun_w2, const float* __restrict__ sun_b2,
                  const float* __restrict__ storm_w1, const float* __restrict__ storm_b1,
                  const float* __restrict__ storm_w2, const float* __restrict__ storm_b2,
                  float* __restrict__ out, int B)
{
    __shared__ unsigned short lists[9*256];
    __shared__ int   counts[9];
    __shared__ float partial[256];
    __shared__ float sunw1s[8], sunb1s[8], sunw2s[8];
    __shared__ float stmw1s[8], stmb1s[8], stmw2s[8];
    __shared__ float consts[4];
    __shared__ int   zflags[2];
    __shared__ unsigned char  gband[48];
    __shared__ unsigned short goff[48];
    __shared__ int   ngroups;

    const int tid = threadIdx.x;
    const int r0  = blockIdx.x * 256;
    const int row = r0 + tid;

    if (tid < 8){
        sunw1s[tid] = softplusf(sun_w1[tid]);
        sunb1s[tid] = sun_b1[tid];
        sunw2s[tid] = softplusf(sun_w2[tid]);
        stmw1s[tid] = softplusf(storm_w1[tid]);
        stmb1s[tid] = storm_b1[tid];
        stmw2s[tid] = softplusf(storm_w2[tid]);
    }
    if (tid == 0){
        consts[0] = sun_b2[0];
        consts[1] = storm_b2[0];
        int z1 = 1, z2 = 1;
        for (int j = 0; j < 64; j++){
            if (sw2[j]  != 0.f) z1 = 0;
            if (stw2[j] != 0.f) z2 = 0;
        }
        zflags[0] = z1; zflags[1] = z2;
        consts[2] = sigmoidf_(sb2[0]);
        consts[3] = sigmoidf_(stb2[0]);
    }
    if (tid < 9) counts[tid] = 0;
    __syncthreads();

    float sfi = x[(size_t)row*18 + 15];
    float kp  = x[(size_t)row*18 + 16];
    int band  = (int)x[(size_t)row*18 + 17];
    band = min(max(band, 0), 8);

    float sunv = consts[0], stmv = consts[1];
    #pragma unroll
    for (int j = 0; j < 8; j++){
        sunv = fmaf(tanhf(fmaf(sfi, sunw1s[j], sunb1s[j])), sunw2s[j], sunv);
        stmv = fmaf(tanhf(fmaf(kp,  stmw1s[j], stmb1s[j])), stmw2s[j], stmv);
    }

    float sg, stg;
    if (zflags[0]) sg = consts[2];
    else {
        float logit = sb2[0];
        const float* tr = g_tbuf + (size_t)row*256;
        for (int j = 0; j < 64; j++){
            float s = sb1[j];
            for (int d = 0; d < 256; d++) s = fmaf(tr[d], sw1[d*64 + j], s);
            logit = fmaf(mishf(s), sw2[j], logit);
        }
        sg = sigmoidf_(logit);
    }
    if (zflags[1]) stg = consts[3];
    else {
        float logit = stb2[0];
        const float* tr = g_tbuf + (size_t)row*256;
        for (int j = 0; j < 64; j++){
            float s = stb1[j];
            for (int d = 0; d < 256; d++) s = fmaf(tr[d], stw1[d*64 + j], s);
            logit = fmaf(mishf(s), stw2[j], logit);
        }
        stg = sigmoidf_(logit);
    }
    partial[tid] = sg*sunv + stg*stmv;

    int pos = atomicAdd(&counts[band], 1);
    lists[band*256 + pos] = (unsigned short)tid;
    __syncthreads();

    if (tid == 0){
        int n = 0;
        for (int k = 0; k < 9; k++){
            int cc = counts[k];
            for (int b = 0; b < cc; b += 8){
                gband[n] = (unsigned char)k;
                goff[n]  = (unsigned short)b;
                n++;
            }
        }
        ngroups = n;
    }
    __syncthreads();

    const int lane = tid & 31, wid = tid >> 5;
    const int ng = ngroups;

    for (int gi = wid; gi < ng; gi += 8){
        const int k    = gband[gi];
        const int base = goff[gi];
        const int mcnt = min(8, counts[k] - base);
        int lr[8];
        #pragma unroll
        for (int j = 0; j < 8; j++)
            lr[j] = lists[k*256 + base + (j < mcnt ? j : mcnt-1)];

        const float* W = hw1 + (size_t)k*32768;

        unsigned long long acc[8][2];
        #pragma unroll
        for (int j = 0; j < 8; j++){ acc[j][0] = 0ull; acc[j][1] = 0ull; }

        for (int d = 0; d < 256; d += 4){
            float4 w0 = __ldg((const float4*)(W + (size_t)(d+0)*128 + lane*4));
            float4 w1 = __ldg((const float4*)(W + (size_t)(d+1)*128 + lane*4));
            float4 w2 = __ldg((const float4*)(W + (size_t)(d+2)*128 + lane*4));
            float4 w3 = __ldg((const float4*)(W + (size_t)(d+3)*128 + lane*4));
            unsigned long long b00 = pack2(w0.x,w0.y), b01 = pack2(w0.z,w0.w);
            unsigned long long b10 = pack2(w1.x,w1.y), b11 = pack2(w1.z,w1.w);
            unsigned long long b20 = pack2(w2.x,w2.y), b21 = pack2(w2.z,w2.w);
            unsigned long long b30 = pack2(w3.x,w3.y), b31 = pack2(w3.z,w3.w);
            #pragma unroll
            for (int j = 0; j < 8; j++){
                float4 tv = __ldg((const float4*)(g_tbuf + (size_t)(r0 + lr[j])*256 + d));
                unsigned long long a0 = pack2(tv.x,tv.x), a1 = pack2(tv.y,tv.y);
                unsigned long long a2 = pack2(tv.z,tv.z), a3 = pack2(tv.w,tv.w);
                fma2(acc[j][0], a0, b00); fma2(acc[j][1], a0, b01);
                fma2(acc[j][0], a1, b10); fma2(acc[j][1], a1, b11);
                fma2(acc[j][0], a2, b20); fma2(acc[j][1], a2, b21);
                fma2(acc[j][0], a3, b30); fma2(acc[j][1], a3, b31);
            }
        }

        const int c0 = lane*4;
        float4 hb1v = __ldg((const float4*)(hb1 + k*128 + c0));
        float4 hw2v = __ldg((const float4*)(hw2 + k*128 + c0));
        float hb2k  = __ldg(&hb2[k]);
        #pragma unroll
        for (int j = 0; j < 8; j++){
            float s = mishf(lo2(acc[j][0]) + hb1v.x) * hw2v.x
                    + mishf(hi2(acc[j][0]) + hb1v.y) * hw2v.y
                    + mishf(lo2(acc[j][1]) + hb1v.z) * hw2v.z
                    + mishf(hi2(acc[j][1]) + hb1v.w) * hw2v.w;
            #pragma unroll
            for (int o = 16; o > 0; o >>= 1)
                s += __shfl_down_sync(0xffffffffu, s, o);
            if (lane == 0 && j < mcnt)
                out[r0 + lr[j]] = s + hb2k + partial[lr[j]];
        }
    }
}

// ---------------------------------------------------------------------------
extern "C" void kernel_launch(void* const* d_in, const int* in_sizes, int n_in,
                              void* d_out, int out_size)
{
    const float* x       = (const float*)d_in[0];
    const float* tw1     = (const float*)d_in[1];
    const float* tb1     = (const float*)d_in[2];
    const float* tw2     = (const float*)d_in[3];
    const float* tb2     = (const float*)d_in[4];
    const float* hw1     = (const float*)d_in[5];
    const float* hb1     = (const float*)d_in[6];
    const float* hw2     = (const float*)d_in[7];
    const float* hb2     = (const float*)d_in[8];
    const float* sw1     = (const float*)d_in[9];
    const float* sb1     = (const float*)d_in[10];
    const float* sw2     = (const float*)d_in[11];
    const float* sb2     = (const float*)d_in[12];
    const float* stw1    = (const float*)d_in[13];
    const float* stb1    = (const float*)d_in[14];
    const float* stw2    = (const float*)d_in[15];
    const float* stb2    = (const float*)d_in[16];
    const float* sun_w1  = (const float*)d_in[17];
    const float* sun_b1  = (const float*)d_in[18];
    const float* sun_w2  = (const float*)d_in[19];
    const float* sun_b2  = (const float*)d_in[20];
    const float* storm_w1= (const float*)d_in[21];
    const float* storm_b1= (const float*)d_in[22];
    const float* storm_w2= (const float*)d_in[23];
    const float* storm_b2= (const float*)d_in[24];
    float* out = (float*)d_out;

    int B = in_sizes[0] / 18;

    const int SMEM1 = 227328;   // 128KB A frags + 64KB B ring + 30KB tw1
    cudaFuncSetAttribute(trunk_kernel,
                         cudaFuncAttributeMaxDynamicSharedMemorySize, SMEM1);

    prep_tw2_kernel<<<512, 256>>>(tw2);
    trunk_kernel<<<B/64, 256, SMEM1>>>(x, tw1, tb1, tb2, B);
    heads_kernel<<<B/256, 256>>>(x, hw1, hb1, hw2, hb2,
                                 sw1, sb1, sw2, sb2,
                                 stw1, stb1, stw2, stb2,
                                 sun_w1, sun_b1, sun_w2, sun_b2,
                                 storm_w1, storm_b1, storm_w2, storm_b2,
                                 out, B);
}

// round 12
// speedup vs baseline: 2.8245x; 1.0585x over previous
#include <cuda_runtime.h>
#include <cuda_bf16.h>
#include <cstdint>

// ---------------------------------------------------------------------------
// IonisGateV26: fused gated MLP.
//  K0 prep : tw2 (512x256 f32) -> bf16 hi/lo "fragment-linear" images in gmem
//            (32 k16-chunks x 16KB; each: hi 8KB | lo 8KB, lane's mma B-regs
//            at lane*8B).
//  K1 trunk: t = mish(mish(x@tw1+tb1)@tw2+tb2) -> g_tbuf.
//            GEMM2 on mma.sync bf16, 3-term hi/lo split, fragment-linear smem,
//            cp.async ring-2 x 32KB stages, ONE sync per stage.
//            mish uses 1 MUFU (EX2) + Newton reciprocal (no RCP MUFU).
//  K2 heads: band-bucketed rows, flattened work-list, fp32 f32x2 + fast mish.
// ---------------------------------------------------------------------------

#define B_MAX 262144
__device__ float g_tbuf[(size_t)B_MAX * 256];            // t scratch, 256MB
__device__ __align__(16) unsigned char g_bw[32 * 16384]; // tw2 frag images 512KB

// ---------------- math helpers ----------------
// fast reciprocal: magic seed + 3 Newton iterations (FMA pipe, no MUFU).
// valid for positive normal d; rel err ~1e-9.
__device__ __forceinline__ float fastrcp(float d){
    float y = __uint_as_float(0x7EF311C3u - __float_as_uint(d));
    y = y * (2.f - d * y);
    y = y * (2.f - d * y);
    y = y * (2.f - d * y);
    return y;
}
__device__ __forceinline__ float mishf(float v){
    // mish(v) = v * n/(n+2), n = e(e+2), e = exp(v).  1 MUFU + FMAs.
    if (v > 20.f) return v;
    float e = __expf(v);
    float n = e * (e + 2.f);
    return v * n * fastrcp(n + 2.f);
}
__device__ __forceinline__ float softplusf(float v){
    if (v > 20.f) return v;
    return log1pf(__expf(v));
}
__device__ __forceinline__ float sigmoidf_(float v){
    return __fdividef(1.f, 1.f + __expf(-v));
}

// ---------------- packed f32x2 helpers (heads kernel) ----------------
__device__ __forceinline__ unsigned long long pack2(float a, float b){
    unsigned long long r;
    asm("mov.b64 %0, {%1, %2};" : "=l"(r)
        : "r"(__float_as_uint(a)), "r"(__float_as_uint(b)));
    return r;
}
__device__ __forceinline__ void fma2(unsigned long long &d,
                                     unsigned long long a, unsigned long long b){
    asm("fma.rn.f32x2 %0, %1, %2, %0;" : "+l"(d) : "l"(a), "l"(b));
}
__device__ __forceinline__ float lo2(unsigned long long v){
    return __uint_as_float((unsigned)(v & 0xffffffffull));
}
__device__ __forceinline__ float hi2(unsigned long long v){
    return __uint_as_float((unsigned)(v >> 32));
}

// ---------------- cp.async helpers ----------------
__device__ __forceinline__ unsigned smem_u32(const void* p){
    unsigned a;
    asm("{ .reg .u64 t; cvta.to.shared.u64 t, %1; cvt.u32.u64 %0, t; }"
        : "=r"(a) : "l"(p));
    return a;
}
__device__ __forceinline__ void cp16(unsigned s, const void* g){
    asm volatile("cp.async.cg.shared.global [%0], [%1], 16;\n" :: "r"(s), "l"(g));
}
__device__ __forceinline__ void cp_commit(){
    asm volatile("cp.async.commit_group;\n" ::: "memory");
}
template<int N> __device__ __forceinline__ void cp_wait(){
    asm volatile("cp.async.wait_group %0;\n" :: "n"(N) : "memory");
}

// ---------------- mma.sync bf16 (baseline PTX, sm_80+) ----------------
__device__ __forceinline__ void mma16816(float* c, const uint4& a, const uint2& b){
    asm("mma.sync.aligned.m16n8k16.row.col.f32.bf16.bf16.f32 "
        "{%0,%1,%2,%3}, {%4,%5,%6,%7}, {%8,%9}, {%0,%1,%2,%3};"
        : "+f"(c[0]), "+f"(c[1]), "+f"(c[2]), "+f"(c[3])
        : "r"(a.x), "r"(a.y), "r"(a.z), "r"(a.w), "r"(b.x), "r"(b.y));
}
__device__ __forceinline__ unsigned packbf(float x, float y){
    __nv_bfloat162 t = __floats2bfloat162_rn(x, y);
    return *(unsigned*)&t;
}

// ---------------------------------------------------------------------------
// Kernel 0: prep tw2 -> fragment-linear bf16 hi/lo images.
// Element (k,n): ktile=k>>4, ntile=n>>3; lane=(n&7)*4+((k&7)>>1);
// reg=(k>>3)&1; byte=(k&1)*2.
// addr = ktile*16384 + [hi:0|lo:8192] + ntile*256 + lane*8 + reg*4 + byte.
// ---------------------------------------------------------------------------
__global__ void prep_tw2_kernel(const float* __restrict__ tw2){
    int idx = blockIdx.x * blockDim.x + threadIdx.x;   // 0..131071
    int k = idx >> 8, n = idx & 255;
    float v = tw2[(size_t)k * 256 + n];
    __nv_bfloat16 hi = __float2bfloat16(v);
    __nv_bfloat16 lo = __float2bfloat16(v - __bfloat162float(hi));
    int kr = k & 15;
    unsigned lane = (unsigned)((n & 7) * 4 + ((kr & 7) >> 1));
    unsigned off  = (unsigned)((k >> 4) * 16384 + (n >> 3) * 256
                    + lane * 8 + ((kr >> 3) & 1) * 4 + (kr & 1) * 2);
    *(__nv_bfloat16*)(g_bw + off)        = hi;
    *(__nv_bfloat16*)(g_bw + off + 8192) = lo;
}

// ---------------------------------------------------------------------------
// Kernel 1: trunk. 64 rows/block, 256 threads (8 warps), 1 block/SM.
// smem: [0:65536) A-hi frags | [65536:131072) A-lo frags
//       [131072:196608) B ring 2 x 32KB stages (each 2 k16-tiles of 16KB,
//                        hi 8KB | lo 8KB per tile)
//       [196608:227328) tw1s (15x512 f32)
// A frag addr: ((ktile*4 + mtile)*32 + lane)*16
// Warp (wm=w>>2, wn=w&3): mtiles wm*2..+1 (32 rows), ntiles wn*8..+7 (64 cols).
// Pipeline stage s (0..15): cp_wait<0> -> sync -> issue chunk s+1 -> compute
// ktiles 2s, 2s+1. Copy of s+1 overlaps compute of s; single barrier both
// publishes chunk s and frees the slot being refilled.
// ---------------------------------------------------------------------------
__global__ __launch_bounds__(256, 1)
void trunk_kernel(const float* __restrict__ x,
                  const float* __restrict__ tw1, const float* __restrict__ tb1,
                  const float* __restrict__ tb2, int B)
{
    extern __shared__ __align__(16) unsigned char smem[];
    const unsigned sbase = smem_u32(smem);
    const unsigned OFF_AH = 0, OFF_AL = 65536, OFF_B = 131072, OFF_TW1 = 196608;
    float* tw1s = (float*)(smem + OFF_TW1);

    const int tid = threadIdx.x;
    const int w   = tid >> 5;
    const int l   = tid & 31;
    const int r0  = blockIdx.x * 64;

    // preload B chunk 0 (32KB) — overlaps GEMM1
    {
        unsigned dst = sbase + OFF_B;
        const unsigned char* src = g_bw;
        #pragma unroll
        for (int i = 0; i < 8; i++){
            int e = tid + i * 256;
            cp16(dst + e * 16, src + e * 16);
        }
        cp_commit();
    }

    // stage tw1 (15x512 f32)
    for (int i = tid; i < 7680; i += 256) tw1s[i] = __ldg(&tw1[i]);
    __syncthreads();

    // ---- GEMM1 (K=15) + mish + hi/lo split -> A frags ----
    {
        const int mt  = w & 3;
        const int kth = (w >> 2) * 16;
        const int m0  = mt * 16 + (l >> 2);
        const int m1  = m0 + 8;
        float xr0[15], xr1[15];
        #pragma unroll
        for (int d = 0; d < 15; d++){
            xr0[d] = __ldg(&x[(size_t)(r0 + m0) * 18 + d]);
            xr1[d] = __ldg(&x[(size_t)(r0 + m1) * 18 + d]);
        }
        #pragma unroll 1
        for (int kt = 0; kt < 16; kt++){
            const int KT = kth + kt;
            const int c0 = KT * 16 + (l & 3) * 2;
            float a00 = __ldg(&tb1[c0]),     a01 = __ldg(&tb1[c0 + 1]);
            float a02 = __ldg(&tb1[c0 + 8]), a03 = __ldg(&tb1[c0 + 9]);
            float a10 = a00, a11 = a01, a12 = a02, a13 = a03;
            #pragma unroll
            for (int d = 0; d < 15; d++){
                float2 wa = *(const float2*)(tw1s + d * 512 + c0);
                float2 wb = *(const float2*)(tw1s + d * 512 + c0 + 8);
                a00 = fmaf(xr0[d], wa.x, a00); a01 = fmaf(xr0[d], wa.y, a01);
                a02 = fmaf(xr0[d], wb.x, a02); a03 = fmaf(xr0[d], wb.y, a03);
                a10 = fmaf(xr1[d], wa.x, a10); a11 = fmaf(xr1[d], wa.y, a11);
                a12 = fmaf(xr1[d], wb.x, a12); a13 = fmaf(xr1[d], wb.y, a13);
            }
            a00 = mishf(a00); a01 = mishf(a01); a02 = mishf(a02); a03 = mishf(a03);
            a10 = mishf(a10); a11 = mishf(a11); a12 = mishf(a12); a13 = mishf(a13);
            uint4 hv;
            hv.x = packbf(a00, a01);
            hv.y = packbf(a10, a11);
            hv.z = packbf(a02, a03);
            hv.w = packbf(a12, a13);
            float r00 = a00 - __bfloat162float(__float2bfloat16(a00));
            float r01 = a01 - __bfloat162float(__float2bfloat16(a01));
            float r02 = a02 - __bfloat162float(__float2bfloat16(a02));
            float r03 = a03 - __bfloat162float(__float2bfloat16(a03));
            float r10 = a10 - __bfloat162float(__float2bfloat16(a10));
            float r11 = a11 - __bfloat162float(__float2bfloat16(a11));
            float r12 = a12 - __bfloat162float(__float2bfloat16(a12));
            float r13 = a13 - __bfloat162float(__float2bfloat16(a13));
            uint4 lv;
            lv.x = packbf(r00, r01); lv.y = packbf(r10, r11);
            lv.z = packbf(r02, r03); lv.w = packbf(r12, r13);
            unsigned fa = (unsigned)(((KT * 4 + mt) * 32 + l) * 16);
            *(uint4*)(smem + OFF_AH + fa) = hv;
            *(uint4*)(smem + OFF_AL + fa) = lv;
        }
    }
    __syncthreads();   // A frags visible to all warps

    // ---- GEMM2 main loop: 16 stages x 2 ktiles, mma.sync bf16, 3 terms ----
    const int wm = w >> 2;
    const int wn = w & 3;
    float acc[2][8][4];
    #pragma unroll
    for (int i = 0; i < 2; i++)
        #pragma unroll
        for (int j = 0; j < 8; j++)
            #pragma unroll
            for (int q = 0; q < 4; q++) acc[i][j][q] = 0.f;

    #pragma unroll 1
    for (int s = 0; s < 16; s++){
        cp_wait<0>();            // chunk s fully landed (this thread's copies)
        __syncthreads();         // publish chunk s to all; prior slot freed
        if (s + 1 < 16){         // refill freed slot with chunk s+1 (overlaps)
            unsigned dst = sbase + OFF_B + (unsigned)(((s + 1) & 1) * 32768);
            const unsigned char* src = g_bw + (size_t)(s + 1) * 32768;
            #pragma unroll
            for (int i = 0; i < 8; i++){
                int e = tid + i * 256;
                cp16(dst + e * 16, src + e * 16);
            }
            cp_commit();
        }

        const unsigned slot = OFF_B + (unsigned)((s & 1) * 32768);
        #pragma unroll
        for (int ktl = 0; ktl < 2; ktl++){
            const int kt = 2 * s + ktl;
            // A fragments (conflict-free LDS.128 at lane*16)
            uint4 ah[2], al[2];
            #pragma unroll
            for (int mt2 = 0; mt2 < 2; mt2++){
                unsigned fa = (unsigned)(((kt * 4 + wm * 2 + mt2) * 32 + l) * 16);
                ah[mt2] = *(const uint4*)(smem + OFF_AH + fa);
                al[mt2] = *(const uint4*)(smem + OFF_AL + fa);
            }
            // B fragments (conflict-free LDS.64 at lane*8)
            const unsigned bb = slot + (unsigned)(ktl * 16384);
            uint2 bh[8], bl[8];
            #pragma unroll
            for (int nt = 0; nt < 8; nt++){
                unsigned fb = bb + (unsigned)(((wn * 8 + nt) * 32 + l) * 8);
                bh[nt] = *(const uint2*)(smem + fb);
                bl[nt] = *(const uint2*)(smem + fb + 8192);
            }
            // term 1: Ahi * Bhi
            #pragma unroll
            for (int mt2 = 0; mt2 < 2; mt2++)
                #pragma unroll
                for (int nt = 0; nt < 8; nt++)
                    mma16816(acc[mt2][nt], ah[mt2], bh[nt]);
            // term 2: Ahi * Blo
            #pragma unroll
            for (int mt2 = 0; mt2 < 2; mt2++)
                #pragma unroll
                for (int nt = 0; nt < 8; nt++)
                    mma16816(acc[mt2][nt], ah[mt2], bl[nt]);
            // term 3: Alo * Bhi
            #pragma unroll
            for (int mt2 = 0; mt2 < 2; mt2++)
                #pragma unroll
                for (int nt = 0; nt < 8; nt++)
                    mma16816(acc[mt2][nt], al[mt2], bh[nt]);
        }
    }

    // ---- epilogue: +tb2, mish, store t (float2 per row-pair) ----
    #pragma unroll
    for (int mt2 = 0; mt2 < 2; mt2++){
        const int rowa = r0 + wm * 32 + mt2 * 16 + (l >> 2);
        const int rowb = rowa + 8;
        #pragma unroll
        for (int nt = 0; nt < 8; nt++){
            const int col = wn * 64 + nt * 8 + (l & 3) * 2;
            float t0 = __ldg(&tb2[col]), t1 = __ldg(&tb2[col + 1]);
            float2 e0, e1;
            e0.x = mishf(acc[mt2][nt][0] + t0);
            e0.y = mishf(acc[mt2][nt][1] + t1);
            e1.x = mishf(acc[mt2][nt][2] + t0);
            e1.y = mishf(acc[mt2][nt][3] + t1);
            *(float2*)(g_tbuf + (size_t)rowa * 256 + col) = e0;
            *(float2*)(g_tbuf + (size_t)rowb * 256 + col) = e1;
        }
    }
}

// ---------------------------------------------------------------------------
// Kernel 2: heads + gates + monotonic MLPs (structure unchanged; fast mish).
// ---------------------------------------------------------------------------
__global__ __launch_bounds__(256, 2)
void heads_kernel(const float* __restrict__ x,
                  const float* __restrict__ hw1, const float* __restrict__ hb1,
                  const float* __restrict__ hw2, const float* __restrict__ hb2,
                  const float* __restrict__ sw1, const float* __restrict__ sb1,
                  const float* __restrict__ sw2, const float* __restrict__ sb2,
                  const float* __restrict__ stw1, const float* __restrict__ stb1,
                  const float* __restrict__ stw2, const float* __restrict__ stb2,
                  const float* __restrict__ sun_w1, const float* __restrict__ sun_b1,
                  const float* __restrict__ sun_w2, const float* __restrict__ sun_b2,
                  const float* __restrict__ storm_w1, const float* __restrict__ storm_b1,
                  const float* __restrict__ storm_w2, const float* __restrict__ storm_b2,
                  float* __restrict__ out, int B)
{
    __shared__ unsigned short lists[9*256];
    __shared__ int   counts[9];
    __shared__ float partial[256];
    __shared__ float sunw1s[8], sunb1s[8], sunw2s[8];
    __shared__ float stmw1s[8], stmb1s[8], stmw2s[8];
    __shared__ float consts[4];
    __shared__ int   zflags[2];
    __shared__ unsigned char  gband[48];
    __shared__ unsigned short goff[48];
    __shared__ int   ngroups;

    const int tid = threadIdx.x;
    const int r0  = blockIdx.x * 256;
    const int row = r0 + tid;

    if (tid < 8){
        sunw1s[tid] = softplusf(sun_w1[tid]);
        sunb1s[tid] = sun_b1[tid];
        sunw2s[tid] = softplusf(sun_w2[tid]);
        stmw1s[tid] = softplusf(storm_w1[tid]);
        stmb1s[tid] = storm_b1[tid];
        stmw2s[tid] = softplusf(storm_w2[tid]);
    }
    if (tid == 0){
        consts[0] = sun_b2[0];
        consts[1] = storm_b2[0];
        int z1 = 1, z2 = 1;
        for (int j = 0; j < 64; j++){
            if (sw2[j]  != 0.f) z1 = 0;
            if (stw2[j] != 0.f) z2 = 0;
        }
        zflags[0] = z1; zflags[1] = z2;
        consts[2] = sigmoidf_(sb2[0]);
        consts[3] = sigmoidf_(stb2[0]);
    }
    if (tid < 9) counts[tid] = 0;
    __syncthreads();

    float sfi = x[(size_t)row*18 + 15];
    float kp  = x[(size_t)row*18 + 16];
    int band  = (int)x[(size_t)row*18 + 17];
    band = min(max(band, 0), 8);

    float sunv = consts[0], stmv = consts[1];
    #pragma unroll
    for (int j = 0; j < 8; j++){
        sunv = fmaf(tanhf(fmaf(sfi, sunw1s[j], sunb1s[j])), sunw2s[j], sunv);
        stmv = fmaf(tanhf(fmaf(kp,  stmw1s[j], stmb1s[j])), stmw2s[j], stmv);
    }

    float sg, stg;
    if (zflags[0]) sg = consts[2];
    else {
        float logit = sb2[0];
        const float* tr = g_tbuf + (size_t)row*256;
        for (int j = 0; j < 64; j++){
            float s = sb1[j];
            for (int d = 0; d < 256; d++) s = fmaf(tr[d], sw1[d*64 + j], s);
            logit = fmaf(mishf(s), sw2[j], logit);
        }
        sg = sigmoidf_(logit);
    }
    if (zflags[1]) stg = consts[3];
    else {
        float logit = stb2[0];
        const float* tr = g_tbuf + (size_t)row*256;
        for (int j = 0; j < 64; j++){
            float s = stb1[j];
            for (int d = 0; d < 256; d++) s = fmaf(tr[d], stw1[d*64 + j], s);
            logit = fmaf(mishf(s), stw2[j], logit);
        }
        stg = sigmoidf_(logit);
    }
    partial[tid] = sg*sunv + stg*stmv;

    int pos = atomicAdd(&counts[band], 1);
    lists[band*256 + pos] = (unsigned short)tid;
    __syncthreads();

    if (tid == 0){
        int n = 0;
        for (int k = 0; k < 9; k++){
            int cc = counts[k];
            for (int b = 0; b < cc; b += 8){
                gband[n] = (unsigned char)k;
                goff[n]  = (unsigned short)b;
                n++;
            }
        }
        ngroups = n;
    }
    __syncthreads();

    const int lane = tid & 31, wid = tid >> 5;
    const int ng = ngroups;

    for (int gi = wid; gi < ng; gi += 8){
        const int k    = gband[gi];
        const int base = goff[gi];
        const int mcnt = min(8, counts[k] - base);
        int lr[8];
        #pragma unroll
        for (int j = 0; j < 8; j++)
            lr[j] = lists[k*256 + base + (j < mcnt ? j : mcnt-1)];

        const float* W = hw1 + (size_t)k*32768;

        unsigned long long acc[8][2];
        #pragma unroll
        for (int j = 0; j < 8; j++){ acc[j][0] = 0ull; acc[j][1] = 0ull; }

        for (int d = 0; d < 256; d += 4){
            float4 w0 = __ldg((const float4*)(W + (size_t)(d+0)*128 + lane*4));
            float4 w1 = __ldg((const float4*)(W + (size_t)(d+1)*128 + lane*4));
            float4 w2 = __ldg((const float4*)(W + (size_t)(d+2)*128 + lane*4));
            float4 w3 = __ldg((const float4*)(W + (size_t)(d+3)*128 + lane*4));
            unsigned long long b00 = pack2(w0.x,w0.y), b01 = pack2(w0.z,w0.w);
            unsigned long long b10 = pack2(w1.x,w1.y), b11 = pack2(w1.z,w1.w);
            unsigned long long b20 = pack2(w2.x,w2.y), b21 = pack2(w2.z,w2.w);
            unsigned long long b30 = pack2(w3.x,w3.y), b31 = pack2(w3.z,w3.w);
            #pragma unroll
            for (int j = 0; j < 8; j++){
                float4 tv = __ldg((const float4*)(g_tbuf + (size_t)(r0 + lr[j])*256 + d));
                unsigned long long a0 = pack2(tv.x,tv.x), a1 = pack2(tv.y,tv.y);
                unsigned long long a2 = pack2(tv.z,tv.z), a3 = pack2(tv.w,tv.w);
                fma2(acc[j][0], a0, b00); fma2(acc[j][1], a0, b01);
                fma2(acc[j][0], a1, b10); fma2(acc[j][1], a1, b11);
                fma2(acc[j][0], a2, b20); fma2(acc[j][1], a2, b21);
                fma2(acc[j][0], a3, b30); fma2(acc[j][1], a3, b31);
            }
        }

        const int c0 = lane*4;
        float4 hb1v = __ldg((const float4*)(hb1 + k*128 + c0));
        float4 hw2v = __ldg((const float4*)(hw2 + k*128 + c0));
        float hb2k  = __ldg(&hb2[k]);
        #pragma unroll
        for (int j = 0; j < 8; j++){
            float s = mishf(lo2(acc[j][0]) + hb1v.x) * hw2v.x
                    + mishf(hi2(acc[j][0]) + hb1v.y) * hw2v.y
                    + mishf(lo2(acc[j][1]) + hb1v.z) * hw2v.z
                    + mishf(hi2(acc[j][1]) + hb1v.w) * hw2v.w;
            #pragma unroll
            for (int o = 16; o > 0; o >>= 1)
                s += __shfl_down_sync(0xffffffffu, s, o);
            if (lane == 0 && j < mcnt)
                out[r0 + lr[j]] = s + hb2k + partial[lr[j]];
        }
    }
}

// ---------------------------------------------------------------------------
extern "C" void kernel_launch(void* const* d_in, const int* in_sizes, int n_in,
                              void* d_out, int out_size)
{
    const float* x       = (const float*)d_in[0];
    const float* tw1     = (const float*)d_in[1];
    const float* tb1     = (const float*)d_in[2];
    const float* tw2     = (const float*)d_in[3];
    const float* tb2     = (const float*)d_in[4];
    const float* hw1     = (const float*)d_in[5];
    const float* hb1     = (const float*)d_in[6];
    const float* hw2     = (const float*)d_in[7];
    const float* hb2     = (const float*)d_in[8];
    const float* sw1     = (const float*)d_in[9];
    const float* sb1     = (const float*)d_in[10];
    const float* sw2     = (const float*)d_in[11];
    const float* sb2     = (const float*)d_in[12];
    const float* stw1    = (const float*)d_in[13];
    const float* stb1    = (const float*)d_in[14];
    const float* stw2    = (const float*)d_in[15];
    const float* stb2    = (const float*)d_in[16];
    const float* sun_w1  = (const float*)d_in[17];
    const float* sun_b1  = (const float*)d_in[18];
    const float* sun_w2  = (const float*)d_in[19];
    const float* sun_b2  = (const float*)d_in[20];
    const float* storm_w1= (const float*)d_in[21];
    const float* storm_b1= (const float*)d_in[22];
    const float* storm_w2= (const float*)d_in[23];
    const float* storm_b2= (const float*)d_in[24];
    float* out = (float*)d_out;

    int B = in_sizes[0] / 18;

    const int SMEM1 = 227328;   // 128KB A frags + 64KB B ring + 30KB tw1
    cudaFuncSetAttribute(trunk_kernel,
                         cudaFuncAttributeMaxDynamicSharedMemorySize, SMEM1);

    prep_tw2_kernel<<<512, 256>>>(tw2);
    trunk_kernel<<<B/64, 256, SMEM1>>>(x, tw1, tb1, tb2, B);
    heads_kernel<<<B/256, 256>>>(x, hw1, hb1, hw2, hb2,
                                 sw1, sb1, sw2, sb2,
                                 stw1, stb1, stw2, stb2,
                                 sun_w1, sun_b1, sun_w2, sun_b2,
                                 storm_w1, storm_b1, storm_w2, storm_b2,
                                 out, B);
}

// round 15
// speedup vs baseline: 3.0579x; 1.0826x over previous
#include <cuda_runtime.h>
#include <cuda_bf16.h>
#include <cstdint>

// ---------------------------------------------------------------------------
// IonisGateV26: fused gated MLP.
//  K0a prep_tw2: tw2 -> bf16 hi/lo fragment-linear images (trunk B).
//  K0b prep_hw1: hw1 -> 9 per-band bf16 hi/lo fragment-linear images (heads B).
//  K1 trunk: t = mish(mish(x@tw1+tb1)@tw2+tb2) -> g_tbuf (unchanged R12:
//            mma.sync bf16 3-term, cp.async ring-2, 1 sync/stage).
//  K2 heads: band-bucketed rows in 16-row groups; head GEMM on mma.sync bf16
//            3-term (A frags on the fly from t, B from prepped images);
//            gates + monotonic MLPs fp32.
// ---------------------------------------------------------------------------

#define B_MAX 262144
__device__ float g_tbuf[(size_t)B_MAX * 256];            // t scratch, 256MB
__device__ __align__(16) unsigned char g_bw[32 * 16384]; // tw2 frag images 512KB
__device__ __align__(16) unsigned char g_hw[9 * 131072]; // hw1 frag images 1.15MB

// ---------------- math helpers ----------------
__device__ __forceinline__ float fastrcp(float d){
    float y = __uint_as_float(0x7EF311C3u - __float_as_uint(d));
    y = y * (2.f - d * y);
    y = y * (2.f - d * y);
    y = y * (2.f - d * y);
    return y;
}
__device__ __forceinline__ float mishf(float v){
    if (v > 20.f) return v;
    float e = __expf(v);
    float n = e * (e + 2.f);
    return v * n * fastrcp(n + 2.f);
}
__device__ __forceinline__ float softplusf(float v){
    if (v > 20.f) return v;
    return log1pf(__expf(v));
}
__device__ __forceinline__ float sigmoidf_(float v){
    return __fdividef(1.f, 1.f + __expf(-v));
}

// ---------------- cp.async helpers ----------------
__device__ __forceinline__ unsigned smem_u32(const void* p){
    unsigned a;
    asm("{ .reg .u64 t; cvta.to.shared.u64 t, %1; cvt.u32.u64 %0, t; }"
        : "=r"(a) : "l"(p));
    return a;
}
__device__ __forceinline__ void cp16(unsigned s, const void* g){
    asm volatile("cp.async.cg.shared.global [%0], [%1], 16;\n" :: "r"(s), "l"(g));
}
__device__ __forceinline__ void cp_commit(){
    asm volatile("cp.async.commit_group;\n" ::: "memory");
}
template<int N> __device__ __forceinline__ void cp_wait(){
    asm volatile("cp.async.wait_group %0;\n" :: "n"(N) : "memory");
}

// ---------------- mma.sync bf16 (baseline PTX, sm_80+) ----------------
__device__ __forceinline__ void mma16816(float* c, const uint4& a, const uint2& b){
    asm("mma.sync.aligned.m16n8k16.row.col.f32.bf16.bf16.f32 "
        "{%0,%1,%2,%3}, {%4,%5,%6,%7}, {%8,%9}, {%0,%1,%2,%3};"
        : "+f"(c[0]), "+f"(c[1]), "+f"(c[2]), "+f"(c[3])
        : "r"(a.x), "r"(a.y), "r"(a.z), "r"(a.w), "r"(b.x), "r"(b.y));
}
__device__ __forceinline__ unsigned packbf(float x, float y){
    __nv_bfloat162 t = __floats2bfloat162_rn(x, y);
    return *(unsigned*)&t;
}
__device__ __forceinline__ float bfhi_lo(unsigned p){   // low half as float
    __nv_bfloat162 t = *(__nv_bfloat162*)&p;
    return __bfloat162float(t.x);
}
__device__ __forceinline__ float bfhi_hi(unsigned p){   // high half as float
    __nv_bfloat162 t = *(__nv_bfloat162*)&p;
    return __bfloat162float(t.y);
}

// ---------------------------------------------------------------------------
// Kernel 0a: prep tw2 -> fragment-linear bf16 hi/lo images (trunk B).
// ---------------------------------------------------------------------------
__global__ void prep_tw2_kernel(const float* __restrict__ tw2){
    int idx = blockIdx.x * blockDim.x + threadIdx.x;   // 0..131071
    int k = idx >> 8, n = idx & 255;
    float v = tw2[(size_t)k * 256 + n];
    __nv_bfloat16 hi = __float2bfloat16(v);
    __nv_bfloat16 lo = __float2bfloat16(v - __bfloat162float(hi));
    int kr = k & 15;
    unsigned lane = (unsigned)((n & 7) * 4 + ((kr & 7) >> 1));
    unsigned off  = (unsigned)((k >> 4) * 16384 + (n >> 3) * 256
                    + lane * 8 + ((kr >> 3) & 1) * 4 + (kr & 1) * 2);
    *(__nv_bfloat16*)(g_bw + off)        = hi;
    *(__nv_bfloat16*)(g_bw + off + 8192) = lo;
}

// ---------------------------------------------------------------------------
// Kernel 0b: prep hw1 -> per-band fragment-linear bf16 hi/lo images (heads B).
// hw1: [band][d(256)][h(128)].  B tile (kt=d>>4, nt=h>>3): lane=(h&7)*4+((d&7)>>1),
// reg=(d>>3)&1, byte=d&1.  Band block: hi 64KB | lo 64KB.
// ---------------------------------------------------------------------------
__global__ void prep_hw1_kernel(const float* __restrict__ hw1){
    int idx = blockIdx.x * blockDim.x + threadIdx.x;   // 0..294911
    if (idx >= 9 * 32768) return;
    int band = idx >> 15, rem = idx & 32767;
    int d = rem >> 7, h = rem & 127;
    float v = hw1[idx];
    __nv_bfloat16 hi = __float2bfloat16(v);
    __nv_bfloat16 lo = __float2bfloat16(v - __bfloat162float(hi));
    int kr = d & 15;
    unsigned lane = (unsigned)((h & 7) * 4 + ((kr & 7) >> 1));
    unsigned off  = (unsigned)(band * 131072 + (d >> 4) * 4096 + (h >> 3) * 256
                    + lane * 8 + ((kr >> 3) & 1) * 4 + (kr & 1) * 2);
    *(__nv_bfloat16*)(g_hw + off)         = hi;
    *(__nv_bfloat16*)(g_hw + off + 65536) = lo;
}

// ---------------------------------------------------------------------------
// Kernel 1: trunk — unchanged from R12 (passing, 3-term bf16 mma, ring-2).
// ---------------------------------------------------------------------------
__global__ __launch_bounds__(256, 1)
void trunk_kernel(const float* __restrict__ x,
                  const float* __restrict__ tw1, const float* __restrict__ tb1,
                  const float* __restrict__ tb2, int B)
{
    extern __shared__ __align__(16) unsigned char smem[];
    const unsigned sbase = smem_u32(smem);
    const unsigned OFF_AH = 0, OFF_AL = 65536, OFF_B = 131072, OFF_TW1 = 196608;
    float* tw1s = (float*)(smem + OFF_TW1);

    const int tid = threadIdx.x;
    const int w   = tid >> 5;
    const int l   = tid & 31;
    const int r0  = blockIdx.x * 64;

    {   // preload B chunk 0 (32KB)
        unsigned dst = sbase + OFF_B;
        const unsigned char* src = g_bw;
        #pragma unroll
        for (int i = 0; i < 8; i++){
            int e = tid + i * 256;
            cp16(dst + e * 16, src + e * 16);
        }
        cp_commit();
    }
    for (int i = tid; i < 7680; i += 256) tw1s[i] = __ldg(&tw1[i]);
    __syncthreads();

    {   // GEMM1 + mish + hi/lo split -> A frags
        const int mt  = w & 3;
        const int kth = (w >> 2) * 16;
        const int m0  = mt * 16 + (l >> 2);
        const int m1  = m0 + 8;
        float xr0[15], xr1[15];
        #pragma unroll
        for (int d = 0; d < 15; d++){
            xr0[d] = __ldg(&x[(size_t)(r0 + m0) * 18 + d]);
            xr1[d] = __ldg(&x[(size_t)(r0 + m1) * 18 + d]);
        }
        #pragma unroll 1
        for (int kt = 0; kt < 16; kt++){
            const int KT = kth + kt;
            const int c0 = KT * 16 + (l & 3) * 2;
            float a00 = __ldg(&tb1[c0]),     a01 = __ldg(&tb1[c0 + 1]);
            float a02 = __ldg(&tb1[c0 + 8]), a03 = __ldg(&tb1[c0 + 9]);
            float a10 = a00, a11 = a01, a12 = a02, a13 = a03;
            #pragma unroll
            for (int d = 0; d < 15; d++){
                float2 wa = *(const float2*)(tw1s + d * 512 + c0);
                float2 wb = *(const float2*)(tw1s + d * 512 + c0 + 8);
                a00 = fmaf(xr0[d], wa.x, a00); a01 = fmaf(xr0[d], wa.y, a01);
                a02 = fmaf(xr0[d], wb.x, a02); a03 = fmaf(xr0[d], wb.y, a03);
                a10 = fmaf(xr1[d], wa.x, a10); a11 = fmaf(xr1[d], wa.y, a11);
                a12 = fmaf(xr1[d], wb.x, a12); a13 = fmaf(xr1[d], wb.y, a13);
            }
            a00 = mishf(a00); a01 = mishf(a01); a02 = mishf(a02); a03 = mishf(a03);
            a10 = mishf(a10); a11 = mishf(a11); a12 = mishf(a12); a13 = mishf(a13);
            uint4 hv;
            hv.x = packbf(a00, a01);
            hv.y = packbf(a10, a11);
            hv.z = packbf(a02, a03);
            hv.w = packbf(a12, a13);
            uint4 lv;
            lv.x = packbf(a00 - bfhi_lo(hv.x), a01 - bfhi_hi(hv.x));
            lv.y = packbf(a10 - bfhi_lo(hv.y), a11 - bfhi_hi(hv.y));
            lv.z = packbf(a02 - bfhi_lo(hv.z), a03 - bfhi_hi(hv.z));
            lv.w = packbf(a12 - bfhi_lo(hv.w), a13 - bfhi_hi(hv.w));
            unsigned fa = (unsigned)(((KT * 4 + mt) * 32 + l) * 16);
            *(uint4*)(smem + OFF_AH + fa) = hv;
            *(uint4*)(smem + OFF_AL + fa) = lv;
        }
    }
    __syncthreads();

    const int wm = w >> 2;
    const int wn = w & 3;
    float acc[2][8][4];
    #pragma unroll
    for (int i = 0; i < 2; i++)
        #pragma unroll
        for (int j = 0; j < 8; j++)
            #pragma unroll
            for (int q = 0; q < 4; q++) acc[i][j][q] = 0.f;

    #pragma unroll 1
    for (int s = 0; s < 16; s++){
        cp_wait<0>();
        __syncthreads();
        if (s + 1 < 16){
            unsigned dst = sbase + OFF_B + (unsigned)(((s + 1) & 1) * 32768);
            const unsigned char* src = g_bw + (size_t)(s + 1) * 32768;
            #pragma unroll
            for (int i = 0; i < 8; i++){
                int e = tid + i * 256;
                cp16(dst + e * 16, src + e * 16);
            }
            cp_commit();
        }
        const unsigned slot = OFF_B + (unsigned)((s & 1) * 32768);
        #pragma unroll
        for (int ktl = 0; ktl < 2; ktl++){
            const int kt = 2 * s + ktl;
            uint4 ah[2], al[2];
            #pragma unroll
            for (int mt2 = 0; mt2 < 2; mt2++){
                unsigned fa = (unsigned)(((kt * 4 + wm * 2 + mt2) * 32 + l) * 16);
                ah[mt2] = *(const uint4*)(smem + OFF_AH + fa);
                al[mt2] = *(const uint4*)(smem + OFF_AL + fa);
            }
            const unsigned bb = slot + (unsigned)(ktl * 16384);
            uint2 bh[8], bl[8];
            #pragma unroll
            for (int nt = 0; nt < 8; nt++){
                unsigned fb = bb + (unsigned)(((wn * 8 + nt) * 32 + l) * 8);
                bh[nt] = *(const uint2*)(smem + fb);
                bl[nt] = *(const uint2*)(smem + fb + 8192);
            }
            #pragma unroll
            for (int mt2 = 0; mt2 < 2; mt2++)
                #pragma unroll
                for (int nt = 0; nt < 8; nt++)
                    mma16816(acc[mt2][nt], ah[mt2], bh[nt]);
            #pragma unroll
            for (int mt2 = 0; mt2 < 2; mt2++)
                #pragma unroll
                for (int nt = 0; nt < 8; nt++)
                    mma16816(acc[mt2][nt], ah[mt2], bl[nt]);
            #pragma unroll
            for (int mt2 = 0; mt2 < 2; mt2++)
                #pragma unroll
                for (int nt = 0; nt < 8; nt++)
                    mma16816(acc[mt2][nt], al[mt2], bh[nt]);
        }
    }

    #pragma unroll
    for (int mt2 = 0; mt2 < 2; mt2++){
        const int rowa = r0 + wm * 32 + mt2 * 16 + (l >> 2);
        const int rowb = rowa + 8;
        #pragma unroll
        for (int nt = 0; nt < 8; nt++){
            const int col = wn * 64 + nt * 8 + (l & 3) * 2;
            float t0 = __ldg(&tb2[col]), t1 = __ldg(&tb2[col + 1]);
            float2 e0, e1;
            e0.x = mishf(acc[mt2][nt][0] + t0);
            e0.y = mishf(acc[mt2][nt][1] + t1);
            e1.x = mishf(acc[mt2][nt][2] + t0);
            e1.y = mishf(acc[mt2][nt][3] + t1);
            *(float2*)(g_tbuf + (size_t)rowa * 256 + col) = e0;
            *(float2*)(g_tbuf + (size_t)rowb * 256 + col) = e1;
        }
    }
}

// ---------------------------------------------------------------------------
// Kernel 2: heads. 512 rows/block, 256 threads, 2 blocks/SM.
// Phase 1: per-row gates + monotonic MLPs (2 rows/thread), band bucketing.
// Phase 2: 16-row same-band groups; head GEMM M=16,N=128,K=256 on mma.sync
// bf16 3-term. A frags on the fly from g_tbuf (f32 -> bf16 hi/lo); B frags
// from g_hw per-band images. Epilogue: mish, hw2 dot, quad shfl reduce.
// ---------------------------------------------------------------------------
__global__ __launch_bounds__(256, 2)
void heads_kernel(const float* __restrict__ x,
                  const float* __restrict__ hb1, const float* __restrict__ hw2,
                  const float* __restrict__ hb2,
                  const float* __restrict__ sw1, const float* __restrict__ sb1,
                  const float* __restrict__ sw2, const float* __restrict__ sb2,
                  const float* __restrict__ stw1, const float* __restrict__ stb1,
                  const float* __restrict__ stw2, const float* __restrict__ stb2,
                  const float* __restrict__ sun_w1, const float* __restrict__ sun_b1,
                  const float* __restrict__ sun_w2, const float* __restrict__ sun_b2,
                  const float* __restrict__ storm_w1, const float* __restrict__ storm_b1,
                  const float* __restrict__ storm_w2, const float* __restrict__ storm_b2,
                  float* __restrict__ out, int B)
{
    __shared__ unsigned short lists[9*512];
    __shared__ int   counts[9];
    __shared__ float partial[512];
    __shared__ float sunw1s[8], sunb1s[8], sunw2s[8];
    __shared__ float stmw1s[8], stmb1s[8], stmw2s[8];
    __shared__ float consts[4];
    __shared__ int   zflags[2];
    __shared__ unsigned char  gband[64];
    __shared__ unsigned short goff[64];
    __shared__ int   ngroups;

    const int tid = threadIdx.x;
    const int r0  = blockIdx.x * 512;

    if (tid < 8){
        sunw1s[tid] = softplusf(sun_w1[tid]);
        sunb1s[tid] = sun_b1[tid];
        sunw2s[tid] = softplusf(sun_w2[tid]);
        stmw1s[tid] = softplusf(storm_w1[tid]);
        stmb1s[tid] = storm_b1[tid];
        stmw2s[tid] = softplusf(storm_w2[tid]);
    }
    if (tid == 0){
        consts[0] = sun_b2[0];
        consts[1] = storm_b2[0];
        int z1 = 1, z2 = 1;
        for (int j = 0; j < 64; j++){
            if (sw2[j]  != 0.f) z1 = 0;
            if (stw2[j] != 0.f) z2 = 0;
        }
        zflags[0] = z1; zflags[1] = z2;
        consts[2] = sigmoidf_(sb2[0]);
        consts[3] = sigmoidf_(stb2[0]);
    }
    if (tid < 9) counts[tid] = 0;
    __syncthreads();

    // ---- phase 1: two rows per thread ----
    #pragma unroll
    for (int rr = 0; rr < 2; rr++){
        const int ridx = tid + rr * 256;
        const int row  = r0 + ridx;
        float sfi = x[(size_t)row*18 + 15];
        float kp  = x[(size_t)row*18 + 16];
        int band  = (int)x[(size_t)row*18 + 17];
        band = min(max(band, 0), 8);

        float sunv = consts[0], stmv = consts[1];
        #pragma unroll
        for (int j = 0; j < 8; j++){
            sunv = fmaf(tanhf(fmaf(sfi, sunw1s[j], sunb1s[j])), sunw2s[j], sunv);
            stmv = fmaf(tanhf(fmaf(kp,  stmw1s[j], stmb1s[j])), stmw2s[j], stmv);
        }
        float sg, stg;
        if (zflags[0]) sg = consts[2];
        else {   // cold, general path
            float logit = sb2[0];
            const float* tr = g_tbuf + (size_t)row*256;
            for (int j = 0; j < 64; j++){
                float s = sb1[j];
                for (int d = 0; d < 256; d++) s = fmaf(tr[d], sw1[d*64 + j], s);
                logit = fmaf(mishf(s), sw2[j], logit);
            }
            sg = sigmoidf_(logit);
        }
        if (zflags[1]) stg = consts[3];
        else {
            float logit = stb2[0];
            const float* tr = g_tbuf + (size_t)row*256;
            for (int j = 0; j < 64; j++){
                float s = stb1[j];
                for (int d = 0; d < 256; d++) s = fmaf(tr[d], stw1[d*64 + j], s);
                logit = fmaf(mishf(s), stw2[j], logit);
            }
            stg = sigmoidf_(logit);
        }
        partial[ridx] = sg*sunv + stg*stmv;
        int pos = atomicAdd(&counts[band], 1);
        lists[band*512 + pos] = (unsigned short)ridx;
    }
    __syncthreads();

    if (tid == 0){
        int n = 0;
        for (int k = 0; k < 9; k++){
            int cc = counts[k];
            for (int b = 0; b < cc; b += 16){
                gband[n] = (unsigned char)k;
                goff[n]  = (unsigned short)b;
                n++;
            }
        }
        ngroups = n;
    }
    __syncthreads();

    const int l   = tid & 31;
    const int wid = tid >> 5;
    const int ng  = ngroups;

    for (int gi = wid; gi < ng; gi += 8){
        const int k    = gband[gi];
        const int base = goff[gi];
        const int mcnt = min(16, counts[k] - base);   // valid rows in group

        const int pa = l >> 2;          // position 0..7  (rows via a0/a2)
        const int pb = pa + 8;          // position 8..15 (rows via a1/a3)
        const int ra = lists[k*512 + base + (pa < mcnt ? pa : mcnt-1)];
        const int rb = lists[k*512 + base + (pb < mcnt ? pb : mcnt-1)];
        const float* tA = g_tbuf + (size_t)(r0 + ra) * 256;
        const float* tB = g_tbuf + (size_t)(r0 + rb) * 256;
        const unsigned char* Wimg = g_hw + (size_t)k * 131072;

        float acc[16][4];
        #pragma unroll
        for (int nt = 0; nt < 16; nt++)
            #pragma unroll
            for (int q = 0; q < 4; q++) acc[nt][q] = 0.f;

        #pragma unroll 1
        for (int kt = 0; kt < 16; kt++){
            const int c0 = kt * 16 + (l & 3) * 2;
            float2 v0 = *(const float2*)(tA + c0);
            float2 v1 = *(const float2*)(tB + c0);
            float2 v2 = *(const float2*)(tA + c0 + 8);
            float2 v3 = *(const float2*)(tB + c0 + 8);
            uint4 ah, al4;
            ah.x = packbf(v0.x, v0.y);
            ah.y = packbf(v1.x, v1.y);
            ah.z = packbf(v2.x, v2.y);
            ah.w = packbf(v3.x, v3.y);
            al4.x = packbf(v0.x - bfhi_lo(ah.x), v0.y - bfhi_hi(ah.x));
            al4.y = packbf(v1.x - bfhi_lo(ah.y), v1.y - bfhi_hi(ah.y));
            al4.z = packbf(v2.x - bfhi_lo(ah.z), v2.y - bfhi_hi(ah.z));
            al4.w = packbf(v3.x - bfhi_lo(ah.w), v3.y - bfhi_hi(ah.w));

            const unsigned char* Wk = Wimg + kt * 4096 + l * 8;
            #pragma unroll 4
            for (int nt = 0; nt < 16; nt++){
                uint2 bh = *(const uint2*)(Wk + nt * 256);
                uint2 bl = *(const uint2*)(Wk + nt * 256 + 65536);
                mma16816(acc[nt], ah,  bh);
                mma16816(acc[nt], ah,  bl);
                mma16816(acc[nt], al4, bh);
            }
        }

        // epilogue: +hb1, mish, *hw2, sum over cols; quad reduce
        float sumA = 0.f, sumB = 0.f;
        #pragma unroll
        for (int nt = 0; nt < 16; nt++){
            const int col = nt * 8 + (l & 3) * 2;
            float2 hb = *(const float2*)(hb1 + k*128 + col);
            float2 hw = *(const float2*)(hw2 + k*128 + col);
            sumA += mishf(acc[nt][0] + hb.x) * hw.x
                  + mishf(acc[nt][1] + hb.y) * hw.y;
            sumB += mishf(acc[nt][2] + hb.x) * hw.x
                  + mishf(acc[nt][3] + hb.y) * hw.y;
        }
        sumA += __shfl_xor_sync(0xffffffffu, sumA, 1);
        sumA += __shfl_xor_sync(0xffffffffu, sumA, 2);
        sumB += __shfl_xor_sync(0xffffffffu, sumB, 1);
        sumB += __shfl_xor_sync(0xffffffffu, sumB, 2);

        float hb2k = __ldg(&hb2[k]);
        if ((l & 3) == 0){
            if (pa < mcnt) out[r0 + ra] = sumA + hb2k + partial[ra];
            if (pb < mcnt) out[r0 + rb] = sumB + hb2k + partial[rb];
        }
    }
}

// ---------------------------------------------------------------------------
extern "C" void kernel_launch(void* const* d_in, const int* in_sizes, int n_in,
                              void* d_out, int out_size)
{
    const float* x       = (const float*)d_in[0];
    const float* tw1     = (const float*)d_in[1];
    const float* tb1     = (const float*)d_in[2];
    const float* tw2     = (const float*)d_in[3];
    const float* tb2     = (const float*)d_in[4];
    const float* hw1     = (const float*)d_in[5];
    const float* hb1     = (const float*)d_in[6];
    const float* hw2     = (const float*)d_in[7];
    const float* hb2     = (const float*)d_in[8];
    const float* sw1     = (const float*)d_in[9];
    const float* sb1     = (const float*)d_in[10];
    const float* sw2     = (const float*)d_in[11];
    const float* sb2     = (const float*)d_in[12];
    const float* stw1    = (const float*)d_in[13];
    const float* stb1    = (const float*)d_in[14];
    const float* stw2    = (const float*)d_in[15];
    const float* stb2    = (const float*)d_in[16];
    const float* sun_w1  = (const float*)d_in[17];
    const float* sun_b1  = (const float*)d_in[18];
    const float* sun_w2  = (const float*)d_in[19];
    const float* sun_b2  = (const float*)d_in[20];
    const float* storm_w1= (const float*)d_in[21];
    const float* storm_b1= (const float*)d_in[22];
    const float* storm_w2= (const float*)d_in[23];
    const float* storm_b2= (const float*)d_in[24];
    float* out = (float*)d_out;

    int B = in_sizes[0] / 18;

    const int SMEM1 = 227328;
    cudaFuncSetAttribute(trunk_kernel,
                         cudaFuncAttributeMaxDynamicSharedMemorySize, SMEM1);

    prep_tw2_kernel<<<512, 256>>>(tw2);
    prep_hw1_kernel<<<1152, 256>>>(hw1);
    trunk_kernel<<<B/64, 256, SMEM1>>>(x, tw1, tb1, tb2, B);
    heads_kernel<<<B/512, 256>>>(x, hb1, hw2, hb2,
                                 sw1, sb1, sw2, sb2,
                                 stw1, stb1, stw2, stb2,
                                 sun_w1, sun_b1, sun_w2, sun_b2,
                                 storm_w1, storm_b1, storm_w2, storm_b2,
                                 out, B);
}

// round 16
// speedup vs baseline: 3.3588x; 1.0984x over previous
#include <cuda_runtime.h>
#include <cuda_bf16.h>
#include <cstdint>

// ---------------------------------------------------------------------------
// IonisGateV26: fused gated MLP.
//  K0a prep_tw2: tw2 -> bf16 hi/lo fragment-linear images (trunk B).
//  K0b prep_hw1: hw1 -> 9 per-band bf16 hi/lo fragment-linear images (heads B).
//  K1 trunk: t = mish(mish(x@tw1+tb1)@tw2+tb2) -> g_tbuf (unchanged R12/R15).
//  K2 heads: band-bucketed rows in 16-row groups, PAIRED per band so each B
//            fragment load serves two groups (halves L2 traffic); head GEMM on
//            mma.sync bf16 3-term; results combined via atomicAdd into out.
// ---------------------------------------------------------------------------

#define B_MAX 262144
__device__ float g_tbuf[(size_t)B_MAX * 256];            // t scratch, 256MB
__device__ __align__(16) unsigned char g_bw[32 * 16384]; // tw2 frag images 512KB
__device__ __align__(16) unsigned char g_hw[9 * 131072]; // hw1 frag images 1.15MB

// ---------------- math helpers ----------------
__device__ __forceinline__ float fastrcp(float d){
    float y = __uint_as_float(0x7EF311C3u - __float_as_uint(d));
    y = y * (2.f - d * y);
    y = y * (2.f - d * y);
    y = y * (2.f - d * y);
    return y;
}
__device__ __forceinline__ float mishf(float v){
    if (v > 20.f) return v;
    float e = __expf(v);
    float n = e * (e + 2.f);
    return v * n * fastrcp(n + 2.f);
}
__device__ __forceinline__ float softplusf(float v){
    if (v > 20.f) return v;
    return log1pf(__expf(v));
}
__device__ __forceinline__ float sigmoidf_(float v){
    return __fdividef(1.f, 1.f + __expf(-v));
}

// ---------------- cp.async helpers ----------------
__device__ __forceinline__ unsigned smem_u32(const void* p){
    unsigned a;
    asm("{ .reg .u64 t; cvta.to.shared.u64 t, %1; cvt.u32.u64 %0, t; }"
        : "=r"(a) : "l"(p));
    return a;
}
__device__ __forceinline__ void cp16(unsigned s, const void* g){
    asm volatile("cp.async.cg.shared.global [%0], [%1], 16;\n" :: "r"(s), "l"(g));
}
__device__ __forceinline__ void cp_commit(){
    asm volatile("cp.async.commit_group;\n" ::: "memory");
}
template<int N> __device__ __forceinline__ void cp_wait(){
    asm volatile("cp.async.wait_group %0;\n" :: "n"(N) : "memory");
}

// ---------------- mma.sync bf16 (baseline PTX, sm_80+) ----------------
__device__ __forceinline__ void mma16816(float* c, const uint4& a, const uint2& b){
    asm("mma.sync.aligned.m16n8k16.row.col.f32.bf16.bf16.f32 "
        "{%0,%1,%2,%3}, {%4,%5,%6,%7}, {%8,%9}, {%0,%1,%2,%3};"
        : "+f"(c[0]), "+f"(c[1]), "+f"(c[2]), "+f"(c[3])
        : "r"(a.x), "r"(a.y), "r"(a.z), "r"(a.w), "r"(b.x), "r"(b.y));
}
__device__ __forceinline__ unsigned packbf(float x, float y){
    __nv_bfloat162 t = __floats2bfloat162_rn(x, y);
    return *(unsigned*)&t;
}
__device__ __forceinline__ float bfhi_lo(unsigned p){
    __nv_bfloat162 t = *(__nv_bfloat162*)&p;
    return __bfloat162float(t.x);
}
__device__ __forceinline__ float bfhi_hi(unsigned p){
    __nv_bfloat162 t = *(__nv_bfloat162*)&p;
    return __bfloat162float(t.y);
}

// ---------------------------------------------------------------------------
// Kernel 0a: prep tw2 -> fragment-linear bf16 hi/lo images (trunk B).
// ---------------------------------------------------------------------------
__global__ void prep_tw2_kernel(const float* __restrict__ tw2){
    int idx = blockIdx.x * blockDim.x + threadIdx.x;
    int k = idx >> 8, n = idx & 255;
    float v = tw2[(size_t)k * 256 + n];
    __nv_bfloat16 hi = __float2bfloat16(v);
    __nv_bfloat16 lo = __float2bfloat16(v - __bfloat162float(hi));
    int kr = k & 15;
    unsigned lane = (unsigned)((n & 7) * 4 + ((kr & 7) >> 1));
    unsigned off  = (unsigned)((k >> 4) * 16384 + (n >> 3) * 256
                    + lane * 8 + ((kr >> 3) & 1) * 4 + (kr & 1) * 2);
    *(__nv_bfloat16*)(g_bw + off)        = hi;
    *(__nv_bfloat16*)(g_bw + off + 8192) = lo;
}

// ---------------------------------------------------------------------------
// Kernel 0b: prep hw1 -> per-band fragment-linear bf16 hi/lo images (heads B).
// ---------------------------------------------------------------------------
__global__ void prep_hw1_kernel(const float* __restrict__ hw1){
    int idx = blockIdx.x * blockDim.x + threadIdx.x;
    if (idx >= 9 * 32768) return;
    int band = idx >> 15, rem = idx & 32767;
    int d = rem >> 7, h = rem & 127;
    float v = hw1[idx];
    __nv_bfloat16 hi = __float2bfloat16(v);
    __nv_bfloat16 lo = __float2bfloat16(v - __bfloat162float(hi));
    int kr = d & 15;
    unsigned lane = (unsigned)((h & 7) * 4 + ((kr & 7) >> 1));
    unsigned off  = (unsigned)(band * 131072 + (d >> 4) * 4096 + (h >> 3) * 256
                    + lane * 8 + ((kr >> 3) & 1) * 4 + (kr & 1) * 2);
    *(__nv_bfloat16*)(g_hw + off)         = hi;
    *(__nv_bfloat16*)(g_hw + off + 65536) = lo;
}

// ---------------------------------------------------------------------------
// Kernel 1: trunk — unchanged (passing, 3-term bf16 mma, ring-2, 1 sync/stage).
// ---------------------------------------------------------------------------
__global__ __launch_bounds__(256, 1)
void trunk_kernel(const float* __restrict__ x,
                  const float* __restrict__ tw1, const float* __restrict__ tb1,
                  const float* __restrict__ tb2, int B)
{
    extern __shared__ __align__(16) unsigned char smem[];
    const unsigned sbase = smem_u32(smem);
    const unsigned OFF_AH = 0, OFF_AL = 65536, OFF_B = 131072, OFF_TW1 = 196608;
    float* tw1s = (float*)(smem + OFF_TW1);

    const int tid = threadIdx.x;
    const int w   = tid >> 5;
    const int l   = tid & 31;
    const int r0  = blockIdx.x * 64;

    {
        unsigned dst = sbase + OFF_B;
        const unsigned char* src = g_bw;
        #pragma unroll
        for (int i = 0; i < 8; i++){
            int e = tid + i * 256;
            cp16(dst + e * 16, src + e * 16);
        }
        cp_commit();
    }
    for (int i = tid; i < 7680; i += 256) tw1s[i] = __ldg(&tw1[i]);
    __syncthreads();

    {
        const int mt  = w & 3;
        const int kth = (w >> 2) * 16;
        const int m0  = mt * 16 + (l >> 2);
        const int m1  = m0 + 8;
        float xr0[15], xr1[15];
        #pragma unroll
        for (int d = 0; d < 15; d++){
            xr0[d] = __ldg(&x[(size_t)(r0 + m0) * 18 + d]);
            xr1[d] = __ldg(&x[(size_t)(r0 + m1) * 18 + d]);
        }
        #pragma unroll 1
        for (int kt = 0; kt < 16; kt++){
            const int KT = kth + kt;
            const int c0 = KT * 16 + (l & 3) * 2;
            float a00 = __ldg(&tb1[c0]),     a01 = __ldg(&tb1[c0 + 1]);
            float a02 = __ldg(&tb1[c0 + 8]), a03 = __ldg(&tb1[c0 + 9]);
            float a10 = a00, a11 = a01, a12 = a02, a13 = a03;
            #pragma unroll
            for (int d = 0; d < 15; d++){
                float2 wa = *(const float2*)(tw1s + d * 512 + c0);
                float2 wb = *(const float2*)(tw1s + d * 512 + c0 + 8);
                a00 = fmaf(xr0[d], wa.x, a00); a01 = fmaf(xr0[d], wa.y, a01);
                a02 = fmaf(xr0[d], wb.x, a02); a03 = fmaf(xr0[d], wb.y, a03);
                a10 = fmaf(xr1[d], wa.x, a10); a11 = fmaf(xr1[d], wa.y, a11);
                a12 = fmaf(xr1[d], wb.x, a12); a13 = fmaf(xr1[d], wb.y, a13);
            }
            a00 = mishf(a00); a01 = mishf(a01); a02 = mishf(a02); a03 = mishf(a03);
            a10 = mishf(a10); a11 = mishf(a11); a12 = mishf(a12); a13 = mishf(a13);
            uint4 hv;
            hv.x = packbf(a00, a01);
            hv.y = packbf(a10, a11);
            hv.z = packbf(a02, a03);
            hv.w = packbf(a12, a13);
            uint4 lv;
            lv.x = packbf(a00 - bfhi_lo(hv.x), a01 - bfhi_hi(hv.x));
            lv.y = packbf(a10 - bfhi_lo(hv.y), a11 - bfhi_hi(hv.y));
            lv.z = packbf(a02 - bfhi_lo(hv.z), a03 - bfhi_hi(hv.z));
            lv.w = packbf(a12 - bfhi_lo(hv.w), a13 - bfhi_hi(hv.w));
            unsigned fa = (unsigned)(((KT * 4 + mt) * 32 + l) * 16);
            *(uint4*)(smem + OFF_AH + fa) = hv;
            *(uint4*)(smem + OFF_AL + fa) = lv;
        }
    }
    __syncthreads();

    const int wm = w >> 2;
    const int wn = w & 3;
    float acc[2][8][4];
    #pragma unroll
    for (int i = 0; i < 2; i++)
        #pragma unroll
        for (int j = 0; j < 8; j++)
            #pragma unroll
            for (int q = 0; q < 4; q++) acc[i][j][q] = 0.f;

    #pragma unroll 1
    for (int s = 0; s < 16; s++){
        cp_wait<0>();
        __syncthreads();
        if (s + 1 < 16){
            unsigned dst = sbase + OFF_B + (unsigned)(((s + 1) & 1) * 32768);
            const unsigned char* src = g_bw + (size_t)(s + 1) * 32768;
            #pragma unroll
            for (int i = 0; i < 8; i++){
                int e = tid + i * 256;
                cp16(dst + e * 16, src + e * 16);
            }
            cp_commit();
        }
        const unsigned slot = OFF_B + (unsigned)((s & 1) * 32768);
        #pragma unroll
        for (int ktl = 0; ktl < 2; ktl++){
            const int kt = 2 * s + ktl;
            uint4 ah[2], al[2];
            #pragma unroll
            for (int mt2 = 0; mt2 < 2; mt2++){
                unsigned fa = (unsigned)(((kt * 4 + wm * 2 + mt2) * 32 + l) * 16);
                ah[mt2] = *(const uint4*)(smem + OFF_AH + fa);
                al[mt2] = *(const uint4*)(smem + OFF_AL + fa);
            }
            const unsigned bb = slot + (unsigned)(ktl * 16384);
            uint2 bh[8], bl[8];
            #pragma unroll
            for (int nt = 0; nt < 8; nt++){
                unsigned fb = bb + (unsigned)(((wn * 8 + nt) * 32 + l) * 8);
                bh[nt] = *(const uint2*)(smem + fb);
                bl[nt] = *(const uint2*)(smem + fb + 8192);
            }
            #pragma unroll
            for (int mt2 = 0; mt2 < 2; mt2++)
                #pragma unroll
                for (int nt = 0; nt < 8; nt++)
                    mma16816(acc[mt2][nt], ah[mt2], bh[nt]);
            #pragma unroll
            for (int mt2 = 0; mt2 < 2; mt2++)
                #pragma unroll
                for (int nt = 0; nt < 8; nt++)
                    mma16816(acc[mt2][nt], ah[mt2], bl[nt]);
            #pragma unroll
            for (int mt2 = 0; mt2 < 2; mt2++)
                #pragma unroll
                for (int nt = 0; nt < 8; nt++)
                    mma16816(acc[mt2][nt], al[mt2], bh[nt]);
        }
    }

    #pragma unroll
    for (int mt2 = 0; mt2 < 2; mt2++){
        const int rowa = r0 + wm * 32 + mt2 * 16 + (l >> 2);
        const int rowb = rowa + 8;
        #pragma unroll
        for (int nt = 0; nt < 8; nt++){
            const int col = wn * 64 + nt * 8 + (l & 3) * 2;
            float t0 = __ldg(&tb2[col]), t1 = __ldg(&tb2[col + 1]);
            float2 e0, e1;
            e0.x = mishf(acc[mt2][nt][0] + t0);
            e0.y = mishf(acc[mt2][nt][1] + t1);
            e1.x = mishf(acc[mt2][nt][2] + t0);
            e1.y = mishf(acc[mt2][nt][3] + t1);
            *(float2*)(g_tbuf + (size_t)rowa * 256 + col) = e0;
            *(float2*)(g_tbuf + (size_t)rowb * 256 + col) = e1;
        }
    }
}

// ---------------------------------------------------------------------------
// Kernel 2: heads. 512 rows/block, 256 threads, 2 blocks/SM.
// Phase 1: per-row gates + monotonic MLPs; writes out = gates + hb2[band];
//          band bucketing.
// Phase 2: same-band 16-row groups PAIRED; work item = (pair, nt-half).
//          Each warp loads B frags once per kt for its 8 N-tiles and uses
//          them for BOTH groups in the pair. Row results combined into out
//          via one atomicAdd per row-half (2 adds/row total, block-local).
// ---------------------------------------------------------------------------
__global__ __launch_bounds__(256, 2)
void heads_kernel(const float* __restrict__ x,
                  const float* __restrict__ hb1, const float* __restrict__ hw2,
                  const float* __restrict__ hb2,
                  const float* __restrict__ sw1, const float* __restrict__ sb1,
                  const float* __restrict__ sw2, const float* __restrict__ sb2,
                  const float* __restrict__ stw1, const float* __restrict__ stb1,
                  const float* __restrict__ stw2, const float* __restrict__ stb2,
                  const float* __restrict__ sun_w1, const float* __restrict__ sun_b1,
                  const float* __restrict__ sun_w2, const float* __restrict__ sun_b2,
                  const float* __restrict__ storm_w1, const float* __restrict__ storm_b1,
                  const float* __restrict__ storm_w2, const float* __restrict__ storm_b2,
                  float* __restrict__ out, int B)
{
    __shared__ unsigned short lists[9*512];
    __shared__ int   counts[9];
    __shared__ float sunw1s[8], sunb1s[8], sunw2s[8];
    __shared__ float stmw1s[8], stmb1s[8], stmw2s[8];
    __shared__ float consts[4];
    __shared__ int   zflags[2];
    __shared__ unsigned char  pband[48];
    __shared__ unsigned short poff0[48], poff1[48];
    __shared__ int   npairs;

    const int tid = threadIdx.x;
    const int r0  = blockIdx.x * 512;

    if (tid < 8){
        sunw1s[tid] = softplusf(sun_w1[tid]);
        sunb1s[tid] = sun_b1[tid];
        sunw2s[tid] = softplusf(sun_w2[tid]);
        stmw1s[tid] = softplusf(storm_w1[tid]);
        stmb1s[tid] = storm_b1[tid];
        stmw2s[tid] = softplusf(storm_w2[tid]);
    }
    if (tid == 0){
        consts[0] = sun_b2[0];
        consts[1] = storm_b2[0];
        int z1 = 1, z2 = 1;
        for (int j = 0; j < 64; j++){
            if (sw2[j]  != 0.f) z1 = 0;
            if (stw2[j] != 0.f) z2 = 0;
        }
        zflags[0] = z1; zflags[1] = z2;
        consts[2] = sigmoidf_(sb2[0]);
        consts[3] = sigmoidf_(stb2[0]);
    }
    if (tid < 9) counts[tid] = 0;
    __syncthreads();

    // ---- phase 1: two rows per thread; out = gates + hb2[band] ----
    #pragma unroll
    for (int rr = 0; rr < 2; rr++){
        const int ridx = tid + rr * 256;
        const int row  = r0 + ridx;
        float sfi = x[(size_t)row*18 + 15];
        float kp  = x[(size_t)row*18 + 16];
        int band  = (int)x[(size_t)row*18 + 17];
        band = min(max(band, 0), 8);

        float sunv = consts[0], stmv = consts[1];
        #pragma unroll
        for (int j = 0; j < 8; j++){
            sunv = fmaf(tanhf(fmaf(sfi, sunw1s[j], sunb1s[j])), sunw2s[j], sunv);
            stmv = fmaf(tanhf(fmaf(kp,  stmw1s[j], stmb1s[j])), stmw2s[j], stmv);
        }
        float sg, stg;
        if (zflags[0]) sg = consts[2];
        else {
            float logit = sb2[0];
            const float* tr = g_tbuf + (size_t)row*256;
            for (int j = 0; j < 64; j++){
                float s = sb1[j];
                for (int d = 0; d < 256; d++) s = fmaf(tr[d], sw1[d*64 + j], s);
                logit = fmaf(mishf(s), sw2[j], logit);
            }
            sg = sigmoidf_(logit);
        }
        if (zflags[1]) stg = consts[3];
        else {
            float logit = stb2[0];
            const float* tr = g_tbuf + (size_t)row*256;
            for (int j = 0; j < 64; j++){
                float s = stb1[j];
                for (int d = 0; d < 256; d++) s = fmaf(tr[d], stw1[d*64 + j], s);
                logit = fmaf(mishf(s), stw2[j], logit);
            }
            stg = sigmoidf_(logit);
        }
        out[row] = sg*sunv + stg*stmv + __ldg(&hb2[band]);
        int pos = atomicAdd(&counts[band], 1);
        lists[band*512 + pos] = (unsigned short)ridx;
    }
    __syncthreads();

    // build same-band group PAIRS
    if (tid == 0){
        int n = 0;
        for (int k = 0; k < 9; k++){
            int gc = (counts[k] + 15) >> 4;     // 16-row groups in band k
            for (int g = 0; g < gc; g += 2){
                pband[n] = (unsigned char)k;
                poff0[n] = (unsigned short)(g * 16);
                poff1[n] = (g + 1 < gc) ? (unsigned short)((g + 1) * 16) : 0xFFFFu;
                n++;
            }
        }
        npairs = n;
    }
    __syncthreads();

    const int l   = tid & 31;
    const int wid = tid >> 5;
    const int np  = npairs;

    for (int wi = wid; wi < np * 2; wi += 8){
        const int pi = wi >> 1;
        const int h  = wi & 1;               // nt half: tiles h*8 .. h*8+7
        const int k  = pband[pi];
        const int b0 = poff0[pi];
        const int b1 = poff1[pi];
        const bool has1 = (b1 != 0xFFFF);
        const int cnt  = counts[k];
        const int m0   = min(16, cnt - b0);
        const int m1   = has1 ? min(16, cnt - b1) : 0;

        const int pa = l >> 2;               // row position 0..7
        const int pb = pa + 8;               // row position 8..15
        const int ra0 = lists[k*512 + b0 + (pa < m0 ? pa : m0-1)];
        const int rb0 = lists[k*512 + b0 + (pb < m0 ? pb : m0-1)];
        const int ra1 = has1 ? lists[k*512 + b1 + (pa < m1 ? pa : m1-1)] : ra0;
        const int rb1 = has1 ? lists[k*512 + b1 + (pb < m1 ? pb : m1-1)] : rb0;
        const float* tA0 = g_tbuf + (size_t)(r0 + ra0) * 256;
        const float* tB0 = g_tbuf + (size_t)(r0 + rb0) * 256;
        const float* tA1 = g_tbuf + (size_t)(r0 + ra1) * 256;
        const float* tB1 = g_tbuf + (size_t)(r0 + rb1) * 256;
        const unsigned char* Wimg = g_hw + (size_t)k * 131072 + (unsigned)(h * 8) * 256;

        float acc0[8][4], acc1[8][4];
        #pragma unroll
        for (int nt = 0; nt < 8; nt++)
            #pragma unroll
            for (int q = 0; q < 4; q++){ acc0[nt][q] = 0.f; acc1[nt][q] = 0.f; }

        #pragma unroll 1
        for (int kt = 0; kt < 16; kt++){
            const int c0 = kt * 16 + (l & 3) * 2;
            // group 0 A frags
            float2 v0 = *(const float2*)(tA0 + c0);
            float2 v1 = *(const float2*)(tB0 + c0);
            float2 v2 = *(const float2*)(tA0 + c0 + 8);
            float2 v3 = *(const float2*)(tB0 + c0 + 8);
            uint4 ah0, al0;
            ah0.x = packbf(v0.x, v0.y); ah0.y = packbf(v1.x, v1.y);
            ah0.z = packbf(v2.x, v2.y); ah0.w = packbf(v3.x, v3.y);
            al0.x = packbf(v0.x - bfhi_lo(ah0.x), v0.y - bfhi_hi(ah0.x));
            al0.y = packbf(v1.x - bfhi_lo(ah0.y), v1.y - bfhi_hi(ah0.y));
            al0.z = packbf(v2.x - bfhi_lo(ah0.z), v2.y - bfhi_hi(ah0.z));
            al0.w = packbf(v3.x - bfhi_lo(ah0.w), v3.y - bfhi_hi(ah0.w));
            // group 1 A frags
            uint4 ah1, al1;
            if (has1){
                float2 u0 = *(const float2*)(tA1 + c0);
                float2 u1 = *(const float2*)(tB1 + c0);
                float2 u2 = *(const float2*)(tA1 + c0 + 8);
                float2 u3 = *(const float2*)(tB1 + c0 + 8);
                ah1.x = packbf(u0.x, u0.y); ah1.y = packbf(u1.x, u1.y);
                ah1.z = packbf(u2.x, u2.y); ah1.w = packbf(u3.x, u3.y);
                al1.x = packbf(u0.x - bfhi_lo(ah1.x), u0.y - bfhi_hi(ah1.x));
                al1.y = packbf(u1.x - bfhi_lo(ah1.y), u1.y - bfhi_hi(ah1.y));
                al1.z = packbf(u2.x - bfhi_lo(ah1.z), u2.y - bfhi_hi(ah1.z));
                al1.w = packbf(u3.x - bfhi_lo(ah1.w), u3.y - bfhi_hi(ah1.w));
            }

            const unsigned char* Wk = Wimg + kt * 4096 + l * 8;
            #pragma unroll
            for (int nt = 0; nt < 8; nt++){
                uint2 bh = *(const uint2*)(Wk + nt * 256);
                uint2 bl = *(const uint2*)(Wk + nt * 256 + 65536);
                mma16816(acc0[nt], ah0, bh);
                mma16816(acc0[nt], ah0, bl);
                mma16816(acc0[nt], al0, bh);
                if (has1){
                    mma16816(acc1[nt], ah1, bh);
                    mma16816(acc1[nt], ah1, bl);
                    mma16816(acc1[nt], al1, bh);
                }
            }
        }

        // epilogue: +hb1, mish, *hw2, sum over this half's cols; quad reduce
        float sA0 = 0.f, sB0 = 0.f, sA1 = 0.f, sB1 = 0.f;
        #pragma unroll
        for (int nt = 0; nt < 8; nt++){
            const int col = (h * 8 + nt) * 8 + (l & 3) * 2;
            float2 hb = *(const float2*)(hb1 + k*128 + col);
            float2 hw = *(const float2*)(hw2 + k*128 + col);
            sA0 += mishf(acc0[nt][0] + hb.x) * hw.x
                 + mishf(acc0[nt][1] + hb.y) * hw.y;
            sB0 += mishf(acc0[nt][2] + hb.x) * hw.x
                 + mishf(acc0[nt][3] + hb.y) * hw.y;
            if (has1){
                sA1 += mishf(acc1[nt][0] + hb.x) * hw.x
                     + mishf(acc1[nt][1] + hb.y) * hw.y;
                sB1 += mishf(acc1[nt][2] + hb.x) * hw.x
                     + mishf(acc1[nt][3] + hb.y) * hw.y;
            }
        }
        sA0 += __shfl_xor_sync(0xffffffffu, sA0, 1);
        sA0 += __shfl_xor_sync(0xffffffffu, sA0, 2);
        sB0 += __shfl_xor_sync(0xffffffffu, sB0, 1);
        sB0 += __shfl_xor_sync(0xffffffffu, sB0, 2);
        if (has1){
            sA1 += __shfl_xor_sync(0xffffffffu, sA1, 1);
            sA1 += __shfl_xor_sync(0xffffffffu, sA1, 2);
            sB1 += __shfl_xor_sync(0xffffffffu, sB1, 1);
            sB1 += __shfl_xor_sync(0xffffffffu, sB1, 2);
        }

        if ((l & 3) == 0){
            if (pa < m0) atomicAdd(&out[r0 + ra0], sA0);
            if (pb < m0) atomicAdd(&out[r0 + rb0], sB0);
            if (has1){
                if (pa < m1) atomicAdd(&out[r0 + ra1], sA1);
                if (pb < m1) atomicAdd(&out[r0 + rb1], sB1);
            }
        }
    }
}

// ---------------------------------------------------------------------------
extern "C" void kernel_launch(void* const* d_in, const int* in_sizes, int n_in,
                              void* d_out, int out_size)
{
    const float* x       = (const float*)d_in[0];
    const float* tw1     = (const float*)d_in[1];
    const float* tb1     = (const float*)d_in[2];
    const float* tw2     = (const float*)d_in[3];
    const float* tb2     = (const float*)d_in[4];
    const float* hw1     = (const float*)d_in[5];
    const float* hb1     = (const float*)d_in[6];
    const float* hw2     = (const float*)d_in[7];
    const float* hb2     = (const float*)d_in[8];
    const float* sw1     = (const float*)d_in[9];
    const float* sb1     = (const float*)d_in[10];
    const float* sw2     = (const float*)d_in[11];
    const float* sb2     = (const float*)d_in[12];
    const float* stw1    = (const float*)d_in[13];
    const float* stb1    = (const float*)d_in[14];
    const float* stw2    = (const float*)d_in[15];
    const float* stb2    = (const float*)d_in[16];
    const float* sun_w1  = (const float*)d_in[17];
    const float* sun_b1  = (const float*)d_in[18];
    const float* sun_w2  = (const float*)d_in[19];
    const float* sun_b2  = (const float*)d_in[20];
    const float* storm_w1= (const float*)d_in[21];
    const float* storm_b1= (const float*)d_in[22];
    const float* storm_w2= (const float*)d_in[23];
    const float* storm_b2= (const float*)d_in[24];
    float* out = (float*)d_out;

    int B = in_sizes[0] / 18;

    const int SMEM1 = 227328;
    cudaFuncSetAttribute(trunk_kernel,
                         cudaFuncAttributeMaxDynamicSharedMemorySize, SMEM1);

    prep_tw2_kernel<<<512, 256>>>(tw2);
    prep_hw1_kernel<<<1152, 256>>>(hw1);
    trunk_kernel<<<B/64, 256, SMEM1>>>(x, tw1, tb1, tb2, B);
    heads_kernel<<<B/512, 256>>>(x, hb1, hw2, hb2,
                                 sw1, sb1, sw2, sb2,
                                 stw1, stb1, stw2, stb2,
                                 sun_w1, sun_b1, sun_w2, sun_b2,
                                 storm_w1, storm_b1, storm_w2, storm_b2,
                                 out, B);
}

// round 17
// speedup vs baseline: 3.5602x; 1.0600x over previous
#include <cuda_runtime.h>
#include <cuda_bf16.h>
#include <cstdint>

// ---------------------------------------------------------------------------
// IonisGateV26: fused gated MLP.
//  K0a prep_tw2: tw2 -> bf16 hi/lo fragment-linear images (trunk B).
//  K0b prep_hw1: hw1 -> 9 per-band bf16 hi/lo fragment-linear images (heads B).
//  K1 trunk: t = mish(mish(x@tw1+tb1)@tw2+tb2) -> g_tbuf.
//            mma.sync bf16 3-term, cp.async ring-2, 1 sync/stage,
//            512 threads (16 warps: wm x wn = 2 x 8) for latency hiding.
//  K2 heads: paired same-band 16-row groups (unchanged R16 pass).
// ---------------------------------------------------------------------------

#define B_MAX 262144
__device__ float g_tbuf[(size_t)B_MAX * 256];            // t scratch, 256MB
__device__ __align__(16) unsigned char g_bw[32 * 16384]; // tw2 frag images 512KB
__device__ __align__(16) unsigned char g_hw[9 * 131072]; // hw1 frag images 1.15MB

// ---------------- math helpers ----------------
__device__ __forceinline__ float fastrcp(float d){
    float y = __uint_as_float(0x7EF311C3u - __float_as_uint(d));
    y = y * (2.f - d * y);
    y = y * (2.f - d * y);
    y = y * (2.f - d * y);
    return y;
}
__device__ __forceinline__ float mishf(float v){
    if (v > 20.f) return v;
    float e = __expf(v);
    float n = e * (e + 2.f);
    return v * n * fastrcp(n + 2.f);
}
__device__ __forceinline__ float softplusf(float v){
    if (v > 20.f) return v;
    return log1pf(__expf(v));
}
__device__ __forceinline__ float sigmoidf_(float v){
    return __fdividef(1.f, 1.f + __expf(-v));
}

// ---------------- cp.async helpers ----------------
__device__ __forceinline__ unsigned smem_u32(const void* p){
    unsigned a;
    asm("{ .reg .u64 t; cvta.to.shared.u64 t, %1; cvt.u32.u64 %0, t; }"
        : "=r"(a) : "l"(p));
    return a;
}
__device__ __forceinline__ void cp16(unsigned s, const void* g){
    asm volatile("cp.async.cg.shared.global [%0], [%1], 16;\n" :: "r"(s), "l"(g));
}
__device__ __forceinline__ void cp_commit(){
    asm volatile("cp.async.commit_group;\n" ::: "memory");
}
template<int N> __device__ __forceinline__ void cp_wait(){
    asm volatile("cp.async.wait_group %0;\n" :: "n"(N) : "memory");
}

// ---------------- mma.sync bf16 (baseline PTX, sm_80+) ----------------
__device__ __forceinline__ void mma16816(float* c, const uint4& a, const uint2& b){
    asm("mma.sync.aligned.m16n8k16.row.col.f32.bf16.bf16.f32 "
        "{%0,%1,%2,%3}, {%4,%5,%6,%7}, {%8,%9}, {%0,%1,%2,%3};"
        : "+f"(c[0]), "+f"(c[1]), "+f"(c[2]), "+f"(c[3])
        : "r"(a.x), "r"(a.y), "r"(a.z), "r"(a.w), "r"(b.x), "r"(b.y));
}
__device__ __forceinline__ unsigned packbf(float x, float y){
    __nv_bfloat162 t = __floats2bfloat162_rn(x, y);
    return *(unsigned*)&t;
}
__device__ __forceinline__ float bfhi_lo(unsigned p){
    __nv_bfloat162 t = *(__nv_bfloat162*)&p;
    return __bfloat162float(t.x);
}
__device__ __forceinline__ float bfhi_hi(unsigned p){
    __nv_bfloat162 t = *(__nv_bfloat162*)&p;
    return __bfloat162float(t.y);
}

// ---------------------------------------------------------------------------
// Kernel 0a: prep tw2 -> fragment-linear bf16 hi/lo images (trunk B).
// ---------------------------------------------------------------------------
__global__ void prep_tw2_kernel(const float* __restrict__ tw2){
    int idx = blockIdx.x * blockDim.x + threadIdx.x;
    int k = idx >> 8, n = idx & 255;
    float v = tw2[(size_t)k * 256 + n];
    __nv_bfloat16 hi = __float2bfloat16(v);
    __nv_bfloat16 lo = __float2bfloat16(v - __bfloat162float(hi));
    int kr = k & 15;
    unsigned lane = (unsigned)((n & 7) * 4 + ((kr & 7) >> 1));
    unsigned off  = (unsigned)((k >> 4) * 16384 + (n >> 3) * 256
                    + lane * 8 + ((kr >> 3) & 1) * 4 + (kr & 1) * 2);
    *(__nv_bfloat16*)(g_bw + off)        = hi;
    *(__nv_bfloat16*)(g_bw + off + 8192) = lo;
}

// ---------------------------------------------------------------------------
// Kernel 0b: prep hw1 -> per-band fragment-linear bf16 hi/lo images (heads B).
// ---------------------------------------------------------------------------
__global__ void prep_hw1_kernel(const float* __restrict__ hw1){
    int idx = blockIdx.x * blockDim.x + threadIdx.x;
    if (idx >= 9 * 32768) return;
    int band = idx >> 15, rem = idx & 32767;
    int d = rem >> 7, h = rem & 127;
    float v = hw1[idx];
    __nv_bfloat16 hi = __float2bfloat16(v);
    __nv_bfloat16 lo = __float2bfloat16(v - __bfloat162float(hi));
    int kr = d & 15;
    unsigned lane = (unsigned)((h & 7) * 4 + ((kr & 7) >> 1));
    unsigned off  = (unsigned)(band * 131072 + (d >> 4) * 4096 + (h >> 3) * 256
                    + lane * 8 + ((kr >> 3) & 1) * 4 + (kr & 1) * 2);
    *(__nv_bfloat16*)(g_hw + off)         = hi;
    *(__nv_bfloat16*)(g_hw + off + 65536) = lo;
}

// ---------------------------------------------------------------------------
// Kernel 1: trunk. 64 rows/block, 512 threads (16 warps), 1 block/SM.
// smem: [0:65536) A-hi | [65536:131072) A-lo | [131072:196608) B ring 2x32KB
//       [196608:227328) tw1s (15x512 f32)
// GEMM1: warp w: mtile mt=w&3, ktile quarter kq=w>>2 (8 ktiles each).
// GEMM2: warp (wm=w>>3, wn=w&7): mtiles wm*2..+1, ntiles wn*4..+3.
// ---------------------------------------------------------------------------
__global__ __launch_bounds__(512, 1)
void trunk_kernel(const float* __restrict__ x,
                  const float* __restrict__ tw1, const float* __restrict__ tb1,
                  const float* __restrict__ tb2, int B)
{
    extern __shared__ __align__(16) unsigned char smem[];
    const unsigned sbase = smem_u32(smem);
    const unsigned OFF_AH = 0, OFF_AL = 65536, OFF_B = 131072, OFF_TW1 = 196608;
    float* tw1s = (float*)(smem + OFF_TW1);

    const int tid = threadIdx.x;
    const int w   = tid >> 5;
    const int l   = tid & 31;
    const int r0  = blockIdx.x * 64;

    {   // preload B chunk 0 (32KB), 4 cp16/thread
        unsigned dst = sbase + OFF_B;
        const unsigned char* src = g_bw;
        #pragma unroll
        for (int i = 0; i < 4; i++){
            int e = tid + i * 512;
            cp16(dst + e * 16, src + e * 16);
        }
        cp_commit();
    }
    for (int i = tid; i < 7680; i += 512) tw1s[i] = __ldg(&tw1[i]);
    __syncthreads();

    {   // GEMM1 (K=15) + mish + hi/lo split -> A frags; 8 ktiles per warp
        const int mt = w & 3;
        const int kq = w >> 2;             // 0..3
        const int m0 = mt * 16 + (l >> 2);
        const int m1 = m0 + 8;
        float xr0[15], xr1[15];
        #pragma unroll
        for (int d = 0; d < 15; d++){
            xr0[d] = __ldg(&x[(size_t)(r0 + m0) * 18 + d]);
            xr1[d] = __ldg(&x[(size_t)(r0 + m1) * 18 + d]);
        }
        #pragma unroll 1
        for (int kt = 0; kt < 8; kt++){
            const int KT = kq * 8 + kt;
            const int c0 = KT * 16 + (l & 3) * 2;
            float a00 = __ldg(&tb1[c0]),     a01 = __ldg(&tb1[c0 + 1]);
            float a02 = __ldg(&tb1[c0 + 8]), a03 = __ldg(&tb1[c0 + 9]);
            float a10 = a00, a11 = a01, a12 = a02, a13 = a03;
            #pragma unroll
            for (int d = 0; d < 15; d++){
                float2 wa = *(const float2*)(tw1s + d * 512 + c0);
                float2 wb = *(const float2*)(tw1s + d * 512 + c0 + 8);
                a00 = fmaf(xr0[d], wa.x, a00); a01 = fmaf(xr0[d], wa.y, a01);
                a02 = fmaf(xr0[d], wb.x, a02); a03 = fmaf(xr0[d], wb.y, a03);
                a10 = fmaf(xr1[d], wa.x, a10); a11 = fmaf(xr1[d], wa.y, a11);
                a12 = fmaf(xr1[d], wb.x, a12); a13 = fmaf(xr1[d], wb.y, a13);
            }
            a00 = mishf(a00); a01 = mishf(a01); a02 = mishf(a02); a03 = mishf(a03);
            a10 = mishf(a10); a11 = mishf(a11); a12 = mishf(a12); a13 = mishf(a13);
            uint4 hv;
            hv.x = packbf(a00, a01);
            hv.y = packbf(a10, a11);
            hv.z = packbf(a02, a03);
            hv.w = packbf(a12, a13);
            uint4 lv;
            lv.x = packbf(a00 - bfhi_lo(hv.x), a01 - bfhi_hi(hv.x));
            lv.y = packbf(a10 - bfhi_lo(hv.y), a11 - bfhi_hi(hv.y));
            lv.z = packbf(a02 - bfhi_lo(hv.z), a03 - bfhi_hi(hv.z));
            lv.w = packbf(a12 - bfhi_lo(hv.w), a13 - bfhi_hi(hv.w));
            unsigned fa = (unsigned)(((KT * 4 + mt) * 32 + l) * 16);
            *(uint4*)(smem + OFF_AH + fa) = hv;
            *(uint4*)(smem + OFF_AL + fa) = lv;
        }
    }
    __syncthreads();

    // ---- GEMM2: 16 stages x 2 ktiles; warp tile 32 rows x 32 cols ----
    const int wm = w >> 3;       // 0..1
    const int wn = w & 7;        // 0..7
    float acc[2][4][4];
    #pragma unroll
    for (int i = 0; i < 2; i++)
        #pragma unroll
        for (int j = 0; j < 4; j++)
            #pragma unroll
            for (int q = 0; q < 4; q++) acc[i][j][q] = 0.f;

    #pragma unroll 1
    for (int s = 0; s < 16; s++){
        cp_wait<0>();
        __syncthreads();
        if (s + 1 < 16){
            unsigned dst = sbase + OFF_B + (unsigned)(((s + 1) & 1) * 32768);
            const unsigned char* src = g_bw + (size_t)(s + 1) * 32768;
            #pragma unroll
            for (int i = 0; i < 4; i++){
                int e = tid + i * 512;
                cp16(dst + e * 16, src + e * 16);
            }
            cp_commit();
        }
        const unsigned slot = OFF_B + (unsigned)((s & 1) * 32768);
        #pragma unroll
        for (int ktl = 0; ktl < 2; ktl++){
            const int kt = 2 * s + ktl;
            uint4 ah[2], al[2];
            #pragma unroll
            for (int mt2 = 0; mt2 < 2; mt2++){
                unsigned fa = (unsigned)(((kt * 4 + wm * 2 + mt2) * 32 + l) * 16);
                ah[mt2] = *(const uint4*)(smem + OFF_AH + fa);
                al[mt2] = *(const uint4*)(smem + OFF_AL + fa);
            }
            const unsigned bb = slot + (unsigned)(ktl * 16384);
            uint2 bh[4], bl[4];
            #pragma unroll
            for (int nt = 0; nt < 4; nt++){
                unsigned fb = bb + (unsigned)(((wn * 4 + nt) * 32 + l) * 8);
                bh[nt] = *(const uint2*)(smem + fb);
                bl[nt] = *(const uint2*)(smem + fb + 8192);
            }
            #pragma unroll
            for (int mt2 = 0; mt2 < 2; mt2++)
                #pragma unroll
                for (int nt = 0; nt < 4; nt++)
                    mma16816(acc[mt2][nt], ah[mt2], bh[nt]);
            #pragma unroll
            for (int mt2 = 0; mt2 < 2; mt2++)
                #pragma unroll
                for (int nt = 0; nt < 4; nt++)
                    mma16816(acc[mt2][nt], ah[mt2], bl[nt]);
            #pragma unroll
            for (int mt2 = 0; mt2 < 2; mt2++)
                #pragma unroll
                for (int nt = 0; nt < 4; nt++)
                    mma16816(acc[mt2][nt], al[mt2], bh[nt]);
        }
    }

    // ---- epilogue: +tb2, mish, store t ----
    #pragma unroll
    for (int mt2 = 0; mt2 < 2; mt2++){
        const int rowa = r0 + wm * 32 + mt2 * 16 + (l >> 2);
        const int rowb = rowa + 8;
        #pragma unroll
        for (int nt = 0; nt < 4; nt++){
            const int col = (wn * 4 + nt) * 8 + (l & 3) * 2;
            float t0 = __ldg(&tb2[col]), t1 = __ldg(&tb2[col + 1]);
            float2 e0, e1;
            e0.x = mishf(acc[mt2][nt][0] + t0);
            e0.y = mishf(acc[mt2][nt][1] + t1);
            e1.x = mishf(acc[mt2][nt][2] + t0);
            e1.y = mishf(acc[mt2][nt][3] + t1);
            *(float2*)(g_tbuf + (size_t)rowa * 256 + col) = e0;
            *(float2*)(g_tbuf + (size_t)rowb * 256 + col) = e1;
        }
    }
}

// ---------------------------------------------------------------------------
// Kernel 2: heads — unchanged R16 (paired groups, atomicAdd combine).
// ---------------------------------------------------------------------------
__global__ __launch_bounds__(256, 2)
void heads_kernel(const float* __restrict__ x,
                  const float* __restrict__ hb1, const float* __restrict__ hw2,
                  const float* __restrict__ hb2,
                  const float* __restrict__ sw1, const float* __restrict__ sb1,
                  const float* __restrict__ sw2, const float* __restrict__ sb2,
                  const float* __restrict__ stw1, const float* __restrict__ stb1,
                  const float* __restrict__ stw2, const float* __restrict__ stb2,
                  const float* __restrict__ sun_w1, const float* __restrict__ sun_b1,
                  const float* __restrict__ sun_w2, const float* __restrict__ sun_b2,
                  const float* __restrict__ storm_w1, const float* __restrict__ storm_b1,
                  const float* __restrict__ storm_w2, const float* __restrict__ storm_b2,
                  float* __restrict__ out, int B)
{
    __shared__ unsigned short lists[9*512];
    __shared__ int   counts[9];
    __shared__ float sunw1s[8], sunb1s[8], sunw2s[8];
    __shared__ float stmw1s[8], stmb1s[8], stmw2s[8];
    __shared__ float consts[4];
    __shared__ int   zflags[2];
    __shared__ unsigned char  pband[48];
    __shared__ unsigned short poff0[48], poff1[48];
    __shared__ int   npairs;

    const int tid = threadIdx.x;
    const int r0  = blockIdx.x * 512;

    if (tid < 8){
        sunw1s[tid] = softplusf(sun_w1[tid]);
        sunb1s[tid] = sun_b1[tid];
        sunw2s[tid] = softplusf(sun_w2[tid]);
        stmw1s[tid] = softplusf(storm_w1[tid]);
        stmb1s[tid] = storm_b1[tid];
        stmw2s[tid] = softplusf(storm_w2[tid]);
    }
    if (tid == 0){
        consts[0] = sun_b2[0];
        consts[1] = storm_b2[0];
        int z1 = 1, z2 = 1;
        for (int j = 0; j < 64; j++){
            if (sw2[j]  != 0.f) z1 = 0;
            if (stw2[j] != 0.f) z2 = 0;
        }
        zflags[0] = z1; zflags[1] = z2;
        consts[2] = sigmoidf_(sb2[0]);
        consts[3] = sigmoidf_(stb2[0]);
    }
    if (tid < 9) counts[tid] = 0;
    __syncthreads();

    #pragma unroll
    for (int rr = 0; rr < 2; rr++){
        const int ridx = tid + rr * 256;
        const int row  = r0 + ridx;
        float sfi = x[(size_t)row*18 + 15];
        float kp  = x[(size_t)row*18 + 16];
        int band  = (int)x[(size_t)row*18 + 17];
        band = min(max(band, 0), 8);

        float sunv = consts[0], stmv = consts[1];
        #pragma unroll
        for (int j = 0; j < 8; j++){
            sunv = fmaf(tanhf(fmaf(sfi, sunw1s[j], sunb1s[j])), sunw2s[j], sunv);
            stmv = fmaf(tanhf(fmaf(kp,  stmw1s[j], stmb1s[j])), stmw2s[j], stmv);
        }
        float sg, stg;
        if (zflags[0]) sg = consts[2];
        else {
            float logit = sb2[0];
            const float* tr = g_tbuf + (size_t)row*256;
            for (int j = 0; j < 64; j++){
                float s = sb1[j];
                for (int d = 0; d < 256; d++) s = fmaf(tr[d], sw1[d*64 + j], s);
                logit = fmaf(mishf(s), sw2[j], logit);
            }
            sg = sigmoidf_(logit);
        }
        if (zflags[1]) stg = consts[3];
        else {
            float logit = stb2[0];
            const float* tr = g_tbuf + (size_t)row*256;
            for (int j = 0; j < 64; j++){
                float s = stb1[j];
                for (int d = 0; d < 256; d++) s = fmaf(tr[d], stw1[d*64 + j], s);
                logit = fmaf(mishf(s), stw2[j], logit);
            }
            stg = sigmoidf_(logit);
        }
        out[row] = sg*sunv + stg*stmv + __ldg(&hb2[band]);
        int pos = atomicAdd(&counts[band], 1);
        lists[band*512 + pos] = (unsigned short)ridx;
    }
    __syncthreads();

    if (tid == 0){
        int n = 0;
        for (int k = 0; k < 9; k++){
            int gc = (counts[k] + 15) >> 4;
            for (int g = 0; g < gc; g += 2){
                pband[n] = (unsigned char)k;
                poff0[n] = (unsigned short)(g * 16);
                poff1[n] = (g + 1 < gc) ? (unsigned short)((g + 1) * 16) : 0xFFFFu;
                n++;
            }
        }
        npairs = n;
    }
    __syncthreads();

    const int l   = tid & 31;
    const int wid = tid >> 5;
    const int np  = npairs;

    for (int wi = wid; wi < np * 2; wi += 8){
        const int pi = wi >> 1;
        const int h  = wi & 1;
        const int k  = pband[pi];
        const int b0 = poff0[pi];
        const int b1 = poff1[pi];
        const bool has1 = (b1 != 0xFFFF);
        const int cnt  = counts[k];
        const int m0   = min(16, cnt - b0);
        const int m1   = has1 ? min(16, cnt - b1) : 0;

        const int pa = l >> 2;
        const int pb = pa + 8;
        const int ra0 = lists[k*512 + b0 + (pa < m0 ? pa : m0-1)];
        const int rb0 = lists[k*512 + b0 + (pb < m0 ? pb : m0-1)];
        const int ra1 = has1 ? lists[k*512 + b1 + (pa < m1 ? pa : m1-1)] : ra0;
        const int rb1 = has1 ? lists[k*512 + b1 + (pb < m1 ? pb : m1-1)] : rb0;
        const float* tA0 = g_tbuf + (size_t)(r0 + ra0) * 256;
        const float* tB0 = g_tbuf + (size_t)(r0 + rb0) * 256;
        const float* tA1 = g_tbuf + (size_t)(r0 + ra1) * 256;
        const float* tB1 = g_tbuf + (size_t)(r0 + rb1) * 256;
        const unsigned char* Wimg = g_hw + (size_t)k * 131072 + (unsigned)(h * 8) * 256;

        float acc0[8][4], acc1[8][4];
        #pragma unroll
        for (int nt = 0; nt < 8; nt++)
            #pragma unroll
            for (int q = 0; q < 4; q++){ acc0[nt][q] = 0.f; acc1[nt][q] = 0.f; }

        #pragma unroll 1
        for (int kt = 0; kt < 16; kt++){
            const int c0 = kt * 16 + (l & 3) * 2;
            float2 v0 = *(const float2*)(tA0 + c0);
            float2 v1 = *(const float2*)(tB0 + c0);
            float2 v2 = *(const float2*)(tA0 + c0 + 8);
            float2 v3 = *(const float2*)(tB0 + c0 + 8);
            uint4 ah0, al0;
            ah0.x = packbf(v0.x, v0.y); ah0.y = packbf(v1.x, v1.y);
            ah0.z = packbf(v2.x, v2.y); ah0.w = packbf(v3.x, v3.y);
            al0.x = packbf(v0.x - bfhi_lo(ah0.x), v0.y - bfhi_hi(ah0.x));
            al0.y = packbf(v1.x - bfhi_lo(ah0.y), v1.y - bfhi_hi(ah0.y));
            al0.z = packbf(v2.x - bfhi_lo(ah0.z), v2.y - bfhi_hi(ah0.z));
            al0.w = packbf(v3.x - bfhi_lo(ah0.w), v3.y - bfhi_hi(ah0.w));
            uint4 ah1, al1;
            if (has1){
                float2 u0 = *(const float2*)(tA1 + c0);
                float2 u1 = *(const float2*)(tB1 + c0);
                float2 u2 = *(const float2*)(tA1 + c0 + 8);
                float2 u3 = *(const float2*)(tB1 + c0 + 8);
                ah1.x = packbf(u0.x, u0.y); ah1.y = packbf(u1.x, u1.y);
                ah1.z = packbf(u2.x, u2.y); ah1.w = packbf(u3.x, u3.y);
                al1.x = packbf(u0.x - bfhi_lo(ah1.x), u0.y - bfhi_hi(ah1.x));
                al1.y = packbf(u1.x - bfhi_lo(ah1.y), u1.y - bfhi_hi(ah1.y));
                al1.z = packbf(u2.x - bfhi_lo(ah1.z), u2.y - bfhi_hi(ah1.z));
                al1.w = packbf(u3.x - bfhi_lo(ah1.w), u3.y - bfhi_hi(ah1.w));
            }

            const unsigned char* Wk = Wimg + kt * 4096 + l * 8;
            #pragma unroll
            for (int nt = 0; nt < 8; nt++){
                uint2 bh = *(const uint2*)(Wk + nt * 256);
                uint2 bl = *(const uint2*)(Wk + nt * 256 + 65536);
                mma16816(acc0[nt], ah0, bh);
                mma16816(acc0[nt], ah0, bl);
                mma16816(acc0[nt], al0, bh);
                if (has1){
                    mma16816(acc1[nt], ah1, bh);
                    mma16816(acc1[nt], ah1, bl);
                    mma16816(acc1[nt], al1, bh);
                }
            }
        }

        float sA0 = 0.f, sB0 = 0.f, sA1 = 0.f, sB1 = 0.f;
        #pragma unroll
        for (int nt = 0; nt < 8; nt++){
            const int col = (h * 8 + nt) * 8 + (l & 3) * 2;
            float2 hb = *(const float2*)(hb1 + k*128 + col);
            float2 hw = *(const float2*)(hw2 + k*128 + col);
            sA0 += mishf(acc0[nt][0] + hb.x) * hw.x
                 + mishf(acc0[nt][1] + hb.y) * hw.y;
            sB0 += mishf(acc0[nt][2] + hb.x) * hw.x
                 + mishf(acc0[nt][3] + hb.y) * hw.y;
            if (has1){
                sA1 += mishf(acc1[nt][0] + hb.x) * hw.x
                     + mishf(acc1[nt][1] + hb.y) * hw.y;
                sB1 += mishf(acc1[nt][2] + hb.x) * hw.x
                     + mishf(acc1[nt][3] + hb.y) * hw.y;
            }
        }
        sA0 += __shfl_xor_sync(0xffffffffu, sA0, 1);
        sA0 += __shfl_xor_sync(0xffffffffu, sA0, 2);
        sB0 += __shfl_xor_sync(0xffffffffu, sB0, 1);
        sB0 += __shfl_xor_sync(0xffffffffu, sB0, 2);
        if (has1){
            sA1 += __shfl_xor_sync(0xffffffffu, sA1, 1);
            sA1 += __shfl_xor_sync(0xffffffffu, sA1, 2);
            sB1 += __shfl_xor_sync(0xffffffffu, sB1, 1);
            sB1 += __shfl_xor_sync(0xffffffffu, sB1, 2);
        }

        if ((l & 3) == 0){
            if (pa < m0) atomicAdd(&out[r0 + ra0], sA0);
            if (pb < m0) atomicAdd(&out[r0 + rb0], sB0);
            if (has1){
                if (pa < m1) atomicAdd(&out[r0 + ra1], sA1);
                if (pb < m1) atomicAdd(&out[r0 + rb1], sB1);
            }
        }
    }
}

// ---------------------------------------------------------------------------
extern "C" void kernel_launch(void* const* d_in, const int* in_sizes, int n_in,
                              void* d_out, int out_size)
{
    const float* x       = (const float*)d_in[0];
    const float* tw1     = (const float*)d_in[1];
    const float* tb1     = (const float*)d_in[2];
    const float* tw2     = (const float*)d_in[3];
    const float* tb2     = (const float*)d_in[4];
    const float* hw1     = (const float*)d_in[5];
    const float* hb1     = (const float*)d_in[6];
    const float* hw2     = (const float*)d_in[7];
    const float* hb2     = (const float*)d_in[8];
    const float* sw1     = (const float*)d_in[9];
    const float* sb1     = (const float*)d_in[10];
    const float* sw2     = (const float*)d_in[11];
    const float* sb2     = (const float*)d_in[12];
    const float* stw1    = (const float*)d_in[13];
    const float* stb1    = (const float*)d_in[14];
    const float* stw2    = (const float*)d_in[15];
    const float* stb2    = (const float*)d_in[16];
    const float* sun_w1  = (const float*)d_in[17];
    const float* sun_b1  = (const float*)d_in[18];
    const float* sun_w2  = (const float*)d_in[19];
    const float* sun_b2  = (const float*)d_in[20];
    const float* storm_w1= (const float*)d_in[21];
    const float* storm_b1= (const float*)d_in[22];
    const float* storm_w2= (const float*)d_in[23];
    const float* storm_b2= (const float*)d_in[24];
    float* out = (float*)d_out;

    int B = in_sizes[0] / 18;

    const int SMEM1 = 227328;
    cudaFuncSetAttribute(trunk_kernel,
                         cudaFuncAttributeMaxDynamicSharedMemorySize, SMEM1);

    prep_tw2_kernel<<<512, 256>>>(tw2);
    prep_hw1_kernel<<<1152, 256>>>(hw1);
    trunk_kernel<<<B/64, 512, SMEM1>>>(x, tw1, tb1, tb2, B);
    heads_kernel<<<B/512, 256>>>(x, hb1, hw2, hb2,
                                 sw1, sb1, sw2, sb2,
                                 stw1, stb1, stw2, stb2,
                                 sun_w1, sun_b1, sun_w2, sun_b2,
                                 storm_w1, storm_b1, storm_w2, storm_b2,
                                 out, B);
}